// round 4
// baseline (speedup 1.0000x reference)
#include <cuda_runtime.h>
#include <cuda_bf16.h>
#include <math.h>
#include <stdint.h>

// Problem constants (fixed by the reference)
#define NNODES 20000
#define NEDGES 320000
#define HDIM   512
#define NPAD   20096            // 157 * 128, padded row count for GEMM tiles

// ---------------- scratch (device globals; no runtime allocation) ----------------
__device__ float           d_s [NNODES * HDIM];       // GEMM output
__device__ __nv_bfloat16   d_Ah[NPAD * HDIM];         // activation hi (bf16), padded
__device__ __nv_bfloat16   d_Al[NPAD * HDIM];         // activation lo (bf16), padded
__device__ __nv_bfloat16   d_Wth[3 * HDIM * HDIM];    // W^T hi (bf16), [N,K], 3 layers
__device__ __nv_bfloat16   d_Wtl[3 * HDIM * HDIM];    // W^T lo
__device__ int      d_counts[NNODES];
__device__ int      d_rowptr[NNODES + 1];
__device__ int      d_rowoff[NNODES];
__device__ int2     d_epack[NEDGES];       // (col, float-bits(val))
__device__ float    d_g[1024];             // accumulated [max | mean] over 3 layers
__device__ unsigned d_gmax[HDIM];
__device__ float    d_gsum[HDIM];

// ================= PTX helpers (generic compute_103-safe) =================
__device__ __forceinline__ uint32_t smem_u32(const void* p) {
    uint32_t a;
    asm("{ .reg .u64 t; cvta.to.shared.u64 t, %1; cvt.u32.u64 %0, t; }" : "=r"(a) : "l"(p));
    return a;
}
__device__ __forceinline__ void cp_async16(uint32_t dst, const void* src) {
    asm volatile("cp.async.cg.shared.global [%0], [%1], 16;" :: "r"(dst), "l"(src));
}
#define CP_COMMIT() asm volatile("cp.async.commit_group;" ::: "memory")
#define CP_WAIT2()  asm volatile("cp.async.wait_group 2;" ::: "memory")

__device__ __forceinline__ void ldsm_x4(uint32_t* r, uint32_t addr) {
    asm volatile("ldmatrix.sync.aligned.m8n8.x4.shared.b16 {%0,%1,%2,%3}, [%4];"
        : "=r"(r[0]), "=r"(r[1]), "=r"(r[2]), "=r"(r[3]) : "r"(addr));
}
__device__ __forceinline__ void mma_bf16(float* c, const uint32_t* a, const uint32_t* b) {
    asm volatile(
        "mma.sync.aligned.m16n8k16.row.col.f32.bf16.bf16.f32 "
        "{%0,%1,%2,%3}, {%4,%5,%6,%7}, {%8,%9}, {%0,%1,%2,%3};"
        : "+f"(c[0]), "+f"(c[1]), "+f"(c[2]), "+f"(c[3])
        : "r"(a[0]), "r"(a[1]), "r"(a[2]), "r"(a[3]), "r"(b[0]), "r"(b[1]));
}

// ---------------- init: zero counters / accumulators ----------------
__global__ void init_kernel() {
    int i = blockIdx.x * blockDim.x + threadIdx.x;
    if (i < NNODES) d_counts[i] = 0;
    if (i < 1024)   d_g[i] = 0.0f;
    if (i < HDIM) { d_gmax[i] = 0u; d_gsum[i] = 0.0f; }
}

// ---------------- CSR build ----------------
__global__ void hist_kernel(const int* __restrict__ rows) {
    int e = blockIdx.x * blockDim.x + threadIdx.x;
    if (e < NEDGES) atomicAdd(&d_counts[rows[e]], 1);
}

// single-block scan over 20000 counts -> rowptr (+ rowoff copy fused)
__global__ void scan_kernel() {
    __shared__ int sums[1024];
    const int CH = 20;
    int t = threadIdx.x;
    int base = t * CH;
    int local[CH];
    int run = 0;
#pragma unroll
    for (int i = 0; i < CH; i++) {
        int idx = base + i;
        int v = (idx < NNODES) ? d_counts[idx] : 0;
        run += v;
        local[i] = run;
    }
    sums[t] = run;
    __syncthreads();
    for (int off = 1; off < 1024; off <<= 1) {
        int v = 0;
        if (t >= off) v = sums[t - off];
        __syncthreads();
        if (t >= off) sums[t] += v;
        __syncthreads();
    }
    int offset = (t > 0) ? sums[t - 1] : 0;
#pragma unroll
    for (int i = 0; i < CH; i++) {
        int idx = base + i;
        if (idx < NNODES) {
            d_rowptr[idx + 1] = offset + local[i];
            d_rowoff[idx] = (i == 0) ? offset : offset + local[i - 1];
        }
    }
    if (t == 0) d_rowptr[0] = 0;
}

__global__ void scatter_kernel(const int* __restrict__ rows,
                               const int* __restrict__ cols,
                               const float* __restrict__ vals) {
    int e = blockIdx.x * blockDim.x + threadIdx.x;
    if (e < NEDGES) {
        int r = rows[e];
        int p = atomicAdd(&d_rowoff[r], 1);
        d_epack[p] = make_int2(cols[e], __float_as_int(vals[e]));
    }
}

// ---------------- fp32 -> bf16 hi/lo split (layer-1 input only) ----------------
__global__ void convert_hilo_kernel(const float* __restrict__ src, int n4) {
    int i = blockIdx.x * blockDim.x + threadIdx.x;
    if (i >= n4) return;
    float4 v = ((const float4*)src)[i];
    __nv_bfloat16 h0 = __float2bfloat16(v.x);
    __nv_bfloat16 h1 = __float2bfloat16(v.y);
    __nv_bfloat16 h2 = __float2bfloat16(v.z);
    __nv_bfloat16 h3 = __float2bfloat16(v.w);
    __nv_bfloat16 l0 = __float2bfloat16(v.x - __bfloat162float(h0));
    __nv_bfloat16 l1 = __float2bfloat16(v.y - __bfloat162float(h1));
    __nv_bfloat16 l2 = __float2bfloat16(v.z - __bfloat162float(h2));
    __nv_bfloat16 l3 = __float2bfloat16(v.w - __bfloat162float(h3));
    ((__nv_bfloat162*)d_Ah)[2 * i]     = __nv_bfloat162(h0, h1);
    ((__nv_bfloat162*)d_Ah)[2 * i + 1] = __nv_bfloat162(h2, h3);
    ((__nv_bfloat162*)d_Al)[2 * i]     = __nv_bfloat162(l0, l1);
    ((__nv_bfloat162*)d_Al)[2 * i + 1] = __nv_bfloat162(l2, l3);
}

// ---------------- W [K,N] -> W^T [N,K] hi/lo, all 3 layers in one launch ----------------
__global__ void transconv_kernel(const float* __restrict__ W1,
                                 const float* __restrict__ W2,
                                 const float* __restrict__ W3) {
    __shared__ float t[32][33];
    const float* W = (blockIdx.z == 0) ? W1 : (blockIdx.z == 1) ? W2 : W3;
    size_t obase = (size_t)blockIdx.z * HDIM * HDIM;
    int bx = blockIdx.x * 32, by = blockIdx.y * 32;
    int x = threadIdx.x, y = threadIdx.y;   // 32 x 8
#pragma unroll
    for (int j = 0; j < 32; j += 8)
        t[y + j][x] = W[(size_t)(by + y + j) * HDIM + bx + x];
    __syncthreads();
#pragma unroll
    for (int j = 0; j < 32; j += 8) {
        float v = t[x][y + j];
        __nv_bfloat16 h = __float2bfloat16(v);
        __nv_bfloat16 l = __float2bfloat16(v - __bfloat162float(h));
        size_t o = obase + (size_t)(bx + y + j) * HDIM + by + x;
        d_Wth[o] = h;
        d_Wtl[o] = l;
    }
}

// ---------------- HMMA bf16x3 GEMM: C[M,512] = A @ B^T ----------------
// A: hi/lo bf16 [NPAD,512] row-major. B: W^T hi/lo bf16 [512,512] ([N,K], K contiguous).
// Block tile 128x128, BK=64, 3-stage cp.async pipeline, 8 warps (2x4), warp tile 64x32.
#define TILE_B   16384                 // 128 rows x 64 bf16 x 2B (128B rows)
#define STAGE_B  (4 * TILE_B)          // Ah, Al, Bh, Bl
#define DYN_SMEM (3 * STAGE_B)         // 196608, 3 stages

__device__ __forceinline__ void load_tile(uint32_t smem_base,
                                          const __nv_bfloat16* __restrict__ src,
                                          int row_base, int k0, int tid) {
    int row = tid >> 1;
    int c0  = (tid & 1) * 4;
    const __nv_bfloat16* g = src + (size_t)(row_base + row) * HDIM + k0;
    uint32_t sb = smem_base + row * 128;
    int xr = row & 7;
#pragma unroll
    for (int c = c0; c < c0 + 4; ++c)
        cp_async16(sb + ((c ^ xr) << 4), g + c * 8);
}

__global__ __launch_bounds__(256, 1)
void gemm_bf16x3_kernel(const __nv_bfloat16* __restrict__ Ah, const __nv_bfloat16* __restrict__ Al,
                        const __nv_bfloat16* __restrict__ Bh, const __nv_bfloat16* __restrict__ Bl,
                        float* __restrict__ C, int M) {
    extern __shared__ __align__(1024) char dsm[];

    const int tid  = threadIdx.x;
    const int wid  = tid >> 5;
    const int lane = tid & 31;
    const int warp_m = wid >> 2;     // 0..1
    const int warp_n = wid & 3;      // 0..3
    const int block_row = blockIdx.x * 128;
    const int block_col = blockIdx.y * 128;

    uint32_t s_base = smem_u32(dsm);

    float acc[4][4][4];
#pragma unroll
    for (int i = 0; i < 4; i++)
#pragma unroll
        for (int j = 0; j < 4; j++)
#pragma unroll
            for (int q = 0; q < 4; q++) acc[i][j][q] = 0.0f;

    // prologue: stages 0 (k0=0) and 1 (k0=64)
#pragma unroll
    for (int p = 0; p < 2; ++p) {
        uint32_t st = s_base + (uint32_t)p * STAGE_B;
        int k0 = p * 64;
        load_tile(st,              Ah, block_row, k0, tid);
        load_tile(st + TILE_B,     Al, block_row, k0, tid);
        load_tile(st + 2 * TILE_B, Bh, block_col, k0, tid);
        load_tile(st + 3 * TILE_B, Bl, block_col, k0, tid);
        CP_COMMIT();
    }

    // per-lane ldmatrix geometry (row&7 invariant under +16-row steps)
    const int a_row  = warp_m * 64 + (lane & 15);
    const int a_half = lane >> 4;
    const int a_x    = a_row & 7;
    const int b_row  = warp_n * 32 + (lane & 15);
    const int b_half = lane >> 4;
    const int b_x    = b_row & 7;

#pragma unroll 1
    for (int c = 0; c < 8; ++c) {
        // issue loads for stage c+2 into buffer (c+2)%3 (free since MMA c-1 done)
        if (c + 2 < 8) {
            uint32_t st2 = s_base + (uint32_t)((c + 2) % 3) * STAGE_B;
            int k0 = (c + 2) * 64;
            load_tile(st2,              Ah, block_row, k0, tid);
            load_tile(st2 + TILE_B,     Al, block_row, k0, tid);
            load_tile(st2 + 2 * TILE_B, Bh, block_col, k0, tid);
            load_tile(st2 + 3 * TILE_B, Bl, block_col, k0, tid);
        }
        CP_COMMIT();                 // empty commits keep group arithmetic uniform
        CP_WAIT2();                  // stage c complete
        __syncthreads();

        uint32_t st  = s_base + (uint32_t)(c % 3) * STAGE_B;
        uint32_t sAh = st;
        uint32_t sAl = st + TILE_B;
        uint32_t sBh = st + 2 * TILE_B;
        uint32_t sBl = st + 3 * TILE_B;

#pragma unroll
        for (int kk = 0; kk < 4; ++kk) {
            uint32_t a_chunk_off = (uint32_t)(((2 * kk + a_half) ^ a_x) << 4);
            uint32_t b_chunk_off = (uint32_t)(((2 * kk + b_half) ^ b_x) << 4);
            uint32_t ah[4][4], al[4][4];
#pragma unroll
            for (int i = 0; i < 4; ++i) {
                uint32_t ro = (uint32_t)(a_row + i * 16) * 128 + a_chunk_off;
                ldsm_x4(ah[i], sAh + ro);
                ldsm_x4(al[i], sAl + ro);
            }
            uint32_t bh[4][2], bl[4][2];
#pragma unroll
            for (int p = 0; p < 2; ++p) {
                uint32_t ro = (uint32_t)(b_row + p * 16) * 128 + b_chunk_off;
                uint32_t r[4];
                ldsm_x4(r, sBh + ro);
                bh[2 * p][0] = r[0]; bh[2 * p][1] = r[2];
                bh[2 * p + 1][0] = r[1]; bh[2 * p + 1][1] = r[3];
                ldsm_x4(r, sBl + ro);
                bl[2 * p][0] = r[0]; bl[2 * p][1] = r[2];
                bl[2 * p + 1][0] = r[1]; bl[2 * p + 1][1] = r[3];
            }
#pragma unroll
            for (int i = 0; i < 4; ++i)
#pragma unroll
                for (int j = 0; j < 4; ++j) {
                    mma_bf16(acc[i][j], ah[i], bh[j]);
                    mma_bf16(acc[i][j], ah[i], bl[j]);
                    mma_bf16(acc[i][j], al[i], bh[j]);
                }
        }
        __syncthreads();
    }

    // epilogue: direct fp32 stores
    const int r_in = lane >> 2;
    const int c_in = (lane & 3) * 2;
#pragma unroll
    for (int i = 0; i < 4; ++i) {
        int row0 = block_row + warp_m * 64 + i * 16 + r_in;
#pragma unroll
        for (int j = 0; j < 4; ++j) {
            int col = block_col + warp_n * 32 + j * 8 + c_in;
            if (row0 < M)
                *(float2*)(C + (size_t)row0 * HDIM + col) = make_float2(acc[i][j][0], acc[i][j][1]);
            if (row0 + 8 < M)
                *(float2*)(C + (size_t)(row0 + 8) * HDIM + col) = make_float2(acc[i][j][2], acc[i][j][3]);
        }
    }
}

// ---------------- CSR SpMM + bias + ReLU + hi/lo split (fused epilogue) ----------------
// one block per row, 128 threads; writes bf16 hi/lo directly (no fp32 h roundtrip)
__global__ __launch_bounds__(128)
void spmm_relu_kernel(const float* __restrict__ bias) {
    int r = blockIdx.x;
    int t = threadIdx.x;
    int beg = d_rowptr[r];
    int end = d_rowptr[r + 1];
    float4 acc = make_float4(0.f, 0.f, 0.f, 0.f);
    int j = beg;
    for (; j + 3 < end; j += 4) {
        int2 e0 = d_epack[j],     e1 = d_epack[j + 1];
        int2 e2 = d_epack[j + 2], e3 = d_epack[j + 3];
        float4 s0 = *(const float4*)(d_s + (size_t)e0.x * HDIM + t * 4);
        float4 s1 = *(const float4*)(d_s + (size_t)e1.x * HDIM + t * 4);
        float4 s2 = *(const float4*)(d_s + (size_t)e2.x * HDIM + t * 4);
        float4 s3 = *(const float4*)(d_s + (size_t)e3.x * HDIM + t * 4);
        float v0 = __int_as_float(e0.y), v1 = __int_as_float(e1.y);
        float v2 = __int_as_float(e2.y), v3 = __int_as_float(e3.y);
        acc.x = fmaf(v0, s0.x, acc.x); acc.y = fmaf(v0, s0.y, acc.y);
        acc.z = fmaf(v0, s0.z, acc.z); acc.w = fmaf(v0, s0.w, acc.w);
        acc.x = fmaf(v1, s1.x, acc.x); acc.y = fmaf(v1, s1.y, acc.y);
        acc.z = fmaf(v1, s1.z, acc.z); acc.w = fmaf(v1, s1.w, acc.w);
        acc.x = fmaf(v2, s2.x, acc.x); acc.y = fmaf(v2, s2.y, acc.y);
        acc.z = fmaf(v2, s2.z, acc.z); acc.w = fmaf(v2, s2.w, acc.w);
        acc.x = fmaf(v3, s3.x, acc.x); acc.y = fmaf(v3, s3.y, acc.y);
        acc.z = fmaf(v3, s3.z, acc.z); acc.w = fmaf(v3, s3.w, acc.w);
    }
    for (; j < end; ++j) {
        int2 e0 = d_epack[j];
        float v0 = __int_as_float(e0.y);
        float4 s0 = *(const float4*)(d_s + (size_t)e0.x * HDIM + t * 4);
        acc.x = fmaf(v0, s0.x, acc.x); acc.y = fmaf(v0, s0.y, acc.y);
        acc.z = fmaf(v0, s0.z, acc.z); acc.w = fmaf(v0, s0.w, acc.w);
    }
    float4 b = *(const float4*)(bias + t * 4);
    float h0 = fmaxf(acc.x + b.x, 0.f);
    float h1 = fmaxf(acc.y + b.y, 0.f);
    float h2 = fmaxf(acc.z + b.z, 0.f);
    float h3 = fmaxf(acc.w + b.w, 0.f);
    __nv_bfloat16 hh0 = __float2bfloat16(h0);
    __nv_bfloat16 hh1 = __float2bfloat16(h1);
    __nv_bfloat16 hh2 = __float2bfloat16(h2);
    __nv_bfloat16 hh3 = __float2bfloat16(h3);
    __nv_bfloat16 ll0 = __float2bfloat16(h0 - __bfloat162float(hh0));
    __nv_bfloat16 ll1 = __float2bfloat16(h1 - __bfloat162float(hh1));
    __nv_bfloat16 ll2 = __float2bfloat16(h2 - __bfloat162float(hh2));
    __nv_bfloat16 ll3 = __float2bfloat16(h3 - __bfloat162float(hh3));
    __nv_bfloat162* H = (__nv_bfloat162*)(d_Ah + (size_t)r * HDIM + t * 4);
    __nv_bfloat162* L = (__nv_bfloat162*)(d_Al + (size_t)r * HDIM + t * 4);
    H[0] = __nv_bfloat162(hh0, hh1);
    H[1] = __nv_bfloat162(hh2, hh3);
    L[0] = __nv_bfloat162(ll0, ll1);
    L[1] = __nv_bfloat162(ll2, ll3);
}

// ---------------- pooling: reads hi/lo (v = hi + lo) ----------------
__global__ __launch_bounds__(256)
void pool_kernel() {
    int f2 = threadIdx.x;               // feature pair 0..255
    const __nv_bfloat162* H = (const __nv_bfloat162*)d_Ah;
    const __nv_bfloat162* L = (const __nv_bfloat162*)d_Al;
    float mx0 = 0.f, mx1 = 0.f, sm0 = 0.f, sm1 = 0.f;
    for (int n = blockIdx.x; n < NNODES; n += gridDim.x) {
        __nv_bfloat162 h = H[(size_t)n * 256 + f2];
        __nv_bfloat162 l = L[(size_t)n * 256 + f2];
        float v0 = __bfloat162float(h.x) + __bfloat162float(l.x);
        float v1 = __bfloat162float(h.y) + __bfloat162float(l.y);
        mx0 = fmaxf(mx0, v0); sm0 += v0;
        mx1 = fmaxf(mx1, v1); sm1 += v1;
    }
    atomicMax(&d_gmax[2 * f2],     __float_as_uint(mx0));   // valid: values >= 0
    atomicMax(&d_gmax[2 * f2 + 1], __float_as_uint(mx1));
    atomicAdd(&d_gsum[2 * f2],     sm0);
    atomicAdd(&d_gsum[2 * f2 + 1], sm1);
}

__global__ void combine_kernel() {
    int f = threadIdx.x;
    d_g[f]       += __uint_as_float(d_gmax[f]);
    d_g[512 + f] += d_gsum[f] * (1.0f / (float)NNODES);
    d_gmax[f] = 0u;
    d_gsum[f] = 0.0f;
}

// ---------------- MLP head + log_softmax ----------------
__global__ __launch_bounds__(128)
void head_kernel(const float* __restrict__ l1W, const float* __restrict__ l1b,
                 const float* __restrict__ l2W, const float* __restrict__ l2b,
                 const float* __restrict__ l3W, const float* __restrict__ l3b,
                 float* __restrict__ out) {
    __shared__ float y1[128];
    __shared__ float y2[64];
    __shared__ float y3[10];
    int t = threadIdx.x;
    {
        float acc = 0.0f;
        for (int i = 0; i < 1024; i++)
            acc = fmaf(d_g[i], l1W[i * 128 + t], acc);
        y1[t] = fmaxf(acc + l1b[t], 0.0f);
    }
    __syncthreads();
    if (t < 64) {
        float acc = 0.0f;
#pragma unroll 8
        for (int i = 0; i < 128; i++)
            acc = fmaf(y1[i], l2W[i * 64 + t], acc);
        y2[t] = fmaxf(acc + l2b[t], 0.0f);
    }
    __syncthreads();
    if (t < 10) {
        float acc = 0.0f;
#pragma unroll
        for (int i = 0; i < 64; i++)
            acc = fmaf(y2[i], l3W[i * 10 + t], acc);
        y3[t] = acc + l3b[t];
    }
    __syncthreads();
    if (t == 0) {
        float m = -1e30f;
#pragma unroll
        for (int j = 0; j < 10; j++) m = fmaxf(m, y3[j]);
        float s = 0.0f;
#pragma unroll
        for (int j = 0; j < 10; j++) s += expf(y3[j] - m);
        float lse = m + logf(s);
#pragma unroll
        for (int j = 0; j < 10; j++) out[j] = y3[j] - lse;
    }
}

// ---------------- launch ----------------
extern "C" void kernel_launch(void* const* d_in, const int* in_sizes, int n_in,
                              void* d_out, int out_size) {
    const float* x        = (const float*)d_in[0];
    const int*   rows     = (const int*)  d_in[1];
    const int*   cols     = (const int*)  d_in[2];
    const float* adj_vals = (const float*)d_in[3];
    const float* W1 = (const float*)d_in[4];
    const float* b1 = (const float*)d_in[5];
    const float* W2 = (const float*)d_in[6];
    const float* b2 = (const float*)d_in[7];
    const float* W3 = (const float*)d_in[8];
    const float* b3 = (const float*)d_in[9];
    const float* l1W = (const float*)d_in[10];
    const float* l1b = (const float*)d_in[11];
    const float* l2W = (const float*)d_in[12];
    const float* l2b = (const float*)d_in[13];
    const float* l3W = (const float*)d_in[14];
    const float* l3b = (const float*)d_in[15];
    float* out = (float*)d_out;

    float* s_g;  cudaGetSymbolAddress((void**)&s_g,  d_s);
    __nv_bfloat16 *Ah_g, *Al_g, *Wth_g, *Wtl_g;
    cudaGetSymbolAddress((void**)&Ah_g,  d_Ah);
    cudaGetSymbolAddress((void**)&Al_g,  d_Al);
    cudaGetSymbolAddress((void**)&Wth_g, d_Wth);
    cudaGetSymbolAddress((void**)&Wtl_g, d_Wtl);

    static bool attr_set = false;
    if (!attr_set) {
        cudaFuncSetAttribute(gemm_bf16x3_kernel,
                             cudaFuncAttributeMaxDynamicSharedMemorySize, DYN_SMEM);
        attr_set = true;
    }

    const size_t WOFF = (size_t)HDIM * HDIM;

    // init + CSR build + weight prep
    init_kernel<<<(NNODES + 255) / 256, 256>>>();
    hist_kernel<<<(NEDGES + 255) / 256, 256>>>(rows);
    scan_kernel<<<1, 1024>>>();
    scatter_kernel<<<(NEDGES + 255) / 256, 256>>>(rows, cols, adj_vals);
    transconv_kernel<<<dim3(16, 16, 3), dim3(32, 8)>>>(W1, W2, W3);
    convert_hilo_kernel<<<(NNODES * HDIM / 4 + 255) / 256, 256>>>(x, NNODES * HDIM / 4);

    dim3 gemm_grid((NNODES + 127) / 128, HDIM / 128);   // (157, 4)

    // layer 1
    gemm_bf16x3_kernel<<<gemm_grid, 256, DYN_SMEM>>>(Ah_g, Al_g, Wth_g, Wtl_g, s_g, NNODES);
    spmm_relu_kernel<<<NNODES, 128>>>(b1);
    pool_kernel<<<256, 256>>>();
    combine_kernel<<<1, 512>>>();

    // layer 2
    gemm_bf16x3_kernel<<<gemm_grid, 256, DYN_SMEM>>>(Ah_g, Al_g, Wth_g + WOFF, Wtl_g + WOFF, s_g, NNODES);
    spmm_relu_kernel<<<NNODES, 128>>>(b2);
    pool_kernel<<<256, 256>>>();
    combine_kernel<<<1, 512>>>();

    // layer 3
    gemm_bf16x3_kernel<<<gemm_grid, 256, DYN_SMEM>>>(Ah_g, Al_g, Wth_g + 2 * WOFF, Wtl_g + 2 * WOFF, s_g, NNODES);
    spmm_relu_kernel<<<NNODES, 128>>>(b3);
    pool_kernel<<<256, 256>>>();
    combine_kernel<<<1, 512>>>();

    // head
    head_kernel<<<1, 128>>>(l1W, l1b, l2W, l2b, l3W, l3b, out);
}

// round 5
// speedup vs baseline: 1.0131x; 1.0131x over previous
#include <cuda_runtime.h>
#include <cuda_bf16.h>
#include <math.h>
#include <stdint.h>

// Problem constants (fixed by the reference)
#define NNODES 20000
#define NEDGES 320000
#define HDIM   512
#define NPAD   20096            // 157 * 128, padded row count for GEMM tiles

// ---------------- scratch (device globals; no runtime allocation) ----------------
__device__ float           d_s [NNODES * HDIM];       // GEMM output
__device__ __nv_bfloat16   d_Ah[NPAD * HDIM];         // activation hi (bf16), padded
__device__ __nv_bfloat16   d_Al[NPAD * HDIM];         // activation lo (bf16), padded
__device__ __nv_bfloat16   d_Wth[3 * HDIM * HDIM];    // W^T hi (bf16), [N,K], 3 layers
__device__ __nv_bfloat16   d_Wtl[3 * HDIM * HDIM];    // W^T lo
__device__ int      d_counts[NNODES];
__device__ int      d_rowptr[NNODES + 1];
__device__ int      d_rowoff[NNODES];
__device__ int2     d_epack[NEDGES];       // (col, float-bits(val))
__device__ float    d_g[1024];             // accumulated [max | mean] over 3 layers
__device__ unsigned d_gmax[HDIM];
__device__ float    d_gsum[HDIM];

// ================= PTX helpers (generic compute_103-safe) =================
__device__ __forceinline__ uint32_t smem_u32(const void* p) {
    uint32_t a;
    asm("{ .reg .u64 t; cvta.to.shared.u64 t, %1; cvt.u32.u64 %0, t; }" : "=r"(a) : "l"(p));
    return a;
}
__device__ __forceinline__ void cp_async16(uint32_t dst, const void* src) {
    asm volatile("cp.async.cg.shared.global [%0], [%1], 16;" :: "r"(dst), "l"(src));
}
#define CP_COMMIT() asm volatile("cp.async.commit_group;" ::: "memory")
#define CP_WAIT1()  asm volatile("cp.async.wait_group 1;" ::: "memory")

__device__ __forceinline__ void ldsm_x4(uint32_t* r, uint32_t addr) {
    asm volatile("ldmatrix.sync.aligned.m8n8.x4.shared.b16 {%0,%1,%2,%3}, [%4];"
        : "=r"(r[0]), "=r"(r[1]), "=r"(r[2]), "=r"(r[3]) : "r"(addr));
}
__device__ __forceinline__ void mma_bf16(float* c, const uint32_t* a, const uint32_t* b) {
    asm volatile(
        "mma.sync.aligned.m16n8k16.row.col.f32.bf16.bf16.f32 "
        "{%0,%1,%2,%3}, {%4,%5,%6,%7}, {%8,%9}, {%0,%1,%2,%3};"
        : "+f"(c[0]), "+f"(c[1]), "+f"(c[2]), "+f"(c[3])
        : "r"(a[0]), "r"(a[1]), "r"(a[2]), "r"(a[3]), "r"(b[0]), "r"(b[1]));
}

// ---------------- init: zero counters / accumulators ----------------
__global__ void init_kernel() {
    int i = blockIdx.x * blockDim.x + threadIdx.x;
    if (i < NNODES) d_counts[i] = 0;
    if (i < 1024)   d_g[i] = 0.0f;
    if (i < HDIM) { d_gmax[i] = 0u; d_gsum[i] = 0.0f; }
}

// ---------------- CSR build ----------------
__global__ void hist_kernel(const int* __restrict__ rows) {
    int e = blockIdx.x * blockDim.x + threadIdx.x;
    if (e < NEDGES) atomicAdd(&d_counts[rows[e]], 1);
}

// single-block scan over 20000 counts -> rowptr (+ rowoff copy fused)
__global__ void scan_kernel() {
    __shared__ int sums[1024];
    const int CH = 20;
    int t = threadIdx.x;
    int base = t * CH;
    int local[CH];
    int run = 0;
#pragma unroll
    for (int i = 0; i < CH; i++) {
        int idx = base + i;
        int v = (idx < NNODES) ? d_counts[idx] : 0;
        run += v;
        local[i] = run;
    }
    sums[t] = run;
    __syncthreads();
    for (int off = 1; off < 1024; off <<= 1) {
        int v = 0;
        if (t >= off) v = sums[t - off];
        __syncthreads();
        if (t >= off) sums[t] += v;
        __syncthreads();
    }
    int offset = (t > 0) ? sums[t - 1] : 0;
#pragma unroll
    for (int i = 0; i < CH; i++) {
        int idx = base + i;
        if (idx < NNODES) {
            d_rowptr[idx + 1] = offset + local[i];
            d_rowoff[idx] = (i == 0) ? offset : offset + local[i - 1];
        }
    }
    if (t == 0) d_rowptr[0] = 0;
}

__global__ void scatter_kernel(const int* __restrict__ rows,
                               const int* __restrict__ cols,
                               const float* __restrict__ vals) {
    int e = blockIdx.x * blockDim.x + threadIdx.x;
    if (e < NEDGES) {
        int r = rows[e];
        int p = atomicAdd(&d_rowoff[r], 1);
        d_epack[p] = make_int2(cols[e], __float_as_int(vals[e]));
    }
}

// ---------------- fp32 -> bf16 hi/lo split (layer-1 input only) ----------------
__global__ void convert_hilo_kernel(const float* __restrict__ src, int n4) {
    int i = blockIdx.x * blockDim.x + threadIdx.x;
    if (i >= n4) return;
    float4 v = ((const float4*)src)[i];
    __nv_bfloat16 h0 = __float2bfloat16(v.x);
    __nv_bfloat16 h1 = __float2bfloat16(v.y);
    __nv_bfloat16 h2 = __float2bfloat16(v.z);
    __nv_bfloat16 h3 = __float2bfloat16(v.w);
    __nv_bfloat16 l0 = __float2bfloat16(v.x - __bfloat162float(h0));
    __nv_bfloat16 l1 = __float2bfloat16(v.y - __bfloat162float(h1));
    __nv_bfloat16 l2 = __float2bfloat16(v.z - __bfloat162float(h2));
    __nv_bfloat16 l3 = __float2bfloat16(v.w - __bfloat162float(h3));
    ((__nv_bfloat162*)d_Ah)[2 * i]     = __nv_bfloat162(h0, h1);
    ((__nv_bfloat162*)d_Ah)[2 * i + 1] = __nv_bfloat162(h2, h3);
    ((__nv_bfloat162*)d_Al)[2 * i]     = __nv_bfloat162(l0, l1);
    ((__nv_bfloat162*)d_Al)[2 * i + 1] = __nv_bfloat162(l2, l3);
}

// ---------------- W [K,N] -> W^T [N,K] hi/lo, all 3 layers in one launch ----------------
__global__ void transconv_kernel(const float* __restrict__ W1,
                                 const float* __restrict__ W2,
                                 const float* __restrict__ W3) {
    __shared__ float t[32][33];
    const float* W = (blockIdx.z == 0) ? W1 : (blockIdx.z == 1) ? W2 : W3;
    size_t obase = (size_t)blockIdx.z * HDIM * HDIM;
    int bx = blockIdx.x * 32, by = blockIdx.y * 32;
    int x = threadIdx.x, y = threadIdx.y;   // 32 x 8
#pragma unroll
    for (int j = 0; j < 32; j += 8)
        t[y + j][x] = W[(size_t)(by + y + j) * HDIM + bx + x];
    __syncthreads();
#pragma unroll
    for (int j = 0; j < 32; j += 8) {
        float v = t[x][y + j];
        __nv_bfloat16 h = __float2bfloat16(v);
        __nv_bfloat16 l = __float2bfloat16(v - __bfloat162float(h));
        size_t o = obase + (size_t)(bx + y + j) * HDIM + by + x;
        d_Wth[o] = h;
        d_Wtl[o] = l;
    }
}

// ---------------- HMMA bf16x3 GEMM: C[M,512] = A @ B^T (round-3 structure) ----------------
// Block tile 128x128, BK=64, 2-stage cp.async double buffer, 8 warps (2x4), warp tile 64x32.
#define TILE_B   16384                 // 128 rows x 64 bf16 x 2B (128B rows)
#define STAGE_B  (4 * TILE_B)          // Ah, Al, Bh, Bl
#define DYN_SMEM (2 * STAGE_B)         // 131072

__device__ __forceinline__ void load_tile(uint32_t smem_base,
                                          const __nv_bfloat16* __restrict__ src,
                                          int row_base, int k0, int tid) {
    int row = tid >> 1;
    int c0  = (tid & 1) * 4;
    const __nv_bfloat16* g = src + (size_t)(row_base + row) * HDIM + k0;
    uint32_t sb = smem_base + row * 128;
    int xr = row & 7;
#pragma unroll
    for (int c = c0; c < c0 + 4; ++c)
        cp_async16(sb + ((c ^ xr) << 4), g + c * 8);
}

__global__ __launch_bounds__(256, 1)
void gemm_bf16x3_kernel(const __nv_bfloat16* __restrict__ Ah, const __nv_bfloat16* __restrict__ Al,
                        const __nv_bfloat16* __restrict__ Bh, const __nv_bfloat16* __restrict__ Bl,
                        float* __restrict__ C, int M) {
    extern __shared__ __align__(1024) char dsm[];

    const int tid  = threadIdx.x;
    const int wid  = tid >> 5;
    const int lane = tid & 31;
    const int warp_m = wid >> 2;     // 0..1
    const int warp_n = wid & 3;      // 0..3
    const int block_row = blockIdx.x * 128;
    const int block_col = blockIdx.y * 128;

    uint32_t s_base = smem_u32(dsm);

    float acc[4][4][4];
#pragma unroll
    for (int i = 0; i < 4; i++)
#pragma unroll
        for (int j = 0; j < 4; j++)
#pragma unroll
            for (int q = 0; q < 4; q++) acc[i][j][q] = 0.0f;

    // prologue: stage 0 (k0=0), stage 1 (k0=64)
    {
        uint32_t st = s_base;
        load_tile(st,              Ah, block_row, 0, tid);
        load_tile(st + TILE_B,     Al, block_row, 0, tid);
        load_tile(st + 2 * TILE_B, Bh, block_col, 0, tid);
        load_tile(st + 3 * TILE_B, Bl, block_col, 0, tid);
        CP_COMMIT();
        st = s_base + STAGE_B;
        load_tile(st,              Ah, block_row, 64, tid);
        load_tile(st + TILE_B,     Al, block_row, 64, tid);
        load_tile(st + 2 * TILE_B, Bh, block_col, 64, tid);
        load_tile(st + 3 * TILE_B, Bl, block_col, 64, tid);
        CP_COMMIT();
    }

    // per-lane ldmatrix geometry (row&7 invariant under +16-row steps)
    const int a_row  = warp_m * 64 + (lane & 15);
    const int a_half = lane >> 4;
    const int a_x    = a_row & 7;
    const int b_row  = warp_n * 32 + (lane & 15);
    const int b_half = lane >> 4;
    const int b_x    = b_row & 7;

#pragma unroll 1
    for (int c = 0; c < 8; ++c) {
        CP_WAIT1();
        __syncthreads();
        uint32_t st  = s_base + (uint32_t)(c & 1) * STAGE_B;
        uint32_t sAh = st;
        uint32_t sAl = st + TILE_B;
        uint32_t sBh = st + 2 * TILE_B;
        uint32_t sBl = st + 3 * TILE_B;

#pragma unroll
        for (int kk = 0; kk < 4; ++kk) {
            uint32_t a_chunk_off = (uint32_t)(((2 * kk + a_half) ^ a_x) << 4);
            uint32_t b_chunk_off = (uint32_t)(((2 * kk + b_half) ^ b_x) << 4);
            uint32_t ah[4][4], al[4][4];
#pragma unroll
            for (int i = 0; i < 4; ++i) {
                uint32_t ro = (uint32_t)(a_row + i * 16) * 128 + a_chunk_off;
                ldsm_x4(ah[i], sAh + ro);
                ldsm_x4(al[i], sAl + ro);
            }
            uint32_t bh[4][2], bl[4][2];
#pragma unroll
            for (int p = 0; p < 2; ++p) {
                uint32_t ro = (uint32_t)(b_row + p * 16) * 128 + b_chunk_off;
                uint32_t r[4];
                ldsm_x4(r, sBh + ro);
                bh[2 * p][0] = r[0]; bh[2 * p][1] = r[2];
                bh[2 * p + 1][0] = r[1]; bh[2 * p + 1][1] = r[3];
                ldsm_x4(r, sBl + ro);
                bl[2 * p][0] = r[0]; bl[2 * p][1] = r[2];
                bl[2 * p + 1][0] = r[1]; bl[2 * p + 1][1] = r[3];
            }
#pragma unroll
            for (int i = 0; i < 4; ++i)
#pragma unroll
                for (int j = 0; j < 4; ++j) {
                    mma_bf16(acc[i][j], ah[i], bh[j]);
                    mma_bf16(acc[i][j], ah[i], bl[j]);
                    mma_bf16(acc[i][j], al[i], bh[j]);
                }
        }
        __syncthreads();
        if (c + 2 < 8) {
            uint32_t st2 = s_base + (uint32_t)(c & 1) * STAGE_B;
            int k0 = (c + 2) * 64;
            load_tile(st2,              Ah, block_row, k0, tid);
            load_tile(st2 + TILE_B,     Al, block_row, k0, tid);
            load_tile(st2 + 2 * TILE_B, Bh, block_col, k0, tid);
            load_tile(st2 + 3 * TILE_B, Bl, block_col, k0, tid);
        }
        CP_COMMIT();
    }

    // epilogue: direct fp32 stores
    const int r_in = lane >> 2;
    const int c_in = (lane & 3) * 2;
#pragma unroll
    for (int i = 0; i < 4; ++i) {
        int row0 = block_row + warp_m * 64 + i * 16 + r_in;
#pragma unroll
        for (int j = 0; j < 4; ++j) {
            int col = block_col + warp_n * 32 + j * 8 + c_in;
            if (row0 < M)
                *(float2*)(C + (size_t)row0 * HDIM + col) = make_float2(acc[i][j][0], acc[i][j][1]);
            if (row0 + 8 < M)
                *(float2*)(C + (size_t)(row0 + 8) * HDIM + col) = make_float2(acc[i][j][2], acc[i][j][3]);
        }
    }
}

// ---------------- CSR SpMM + bias + ReLU + hi/lo split (fused epilogue) ----------------
__global__ __launch_bounds__(128)
void spmm_relu_kernel(const float* __restrict__ bias) {
    int r = blockIdx.x;
    int t = threadIdx.x;
    int beg = d_rowptr[r];
    int end = d_rowptr[r + 1];
    float4 acc = make_float4(0.f, 0.f, 0.f, 0.f);
    int j = beg;
    for (; j + 3 < end; j += 4) {
        int2 e0 = d_epack[j],     e1 = d_epack[j + 1];
        int2 e2 = d_epack[j + 2], e3 = d_epack[j + 3];
        float4 s0 = *(const float4*)(d_s + (size_t)e0.x * HDIM + t * 4);
        float4 s1 = *(const float4*)(d_s + (size_t)e1.x * HDIM + t * 4);
        float4 s2 = *(const float4*)(d_s + (size_t)e2.x * HDIM + t * 4);
        float4 s3 = *(const float4*)(d_s + (size_t)e3.x * HDIM + t * 4);
        float v0 = __int_as_float(e0.y), v1 = __int_as_float(e1.y);
        float v2 = __int_as_float(e2.y), v3 = __int_as_float(e3.y);
        acc.x = fmaf(v0, s0.x, acc.x); acc.y = fmaf(v0, s0.y, acc.y);
        acc.z = fmaf(v0, s0.z, acc.z); acc.w = fmaf(v0, s0.w, acc.w);
        acc.x = fmaf(v1, s1.x, acc.x); acc.y = fmaf(v1, s1.y, acc.y);
        acc.z = fmaf(v1, s1.z, acc.z); acc.w = fmaf(v1, s1.w, acc.w);
        acc.x = fmaf(v2, s2.x, acc.x); acc.y = fmaf(v2, s2.y, acc.y);
        acc.z = fmaf(v2, s2.z, acc.z); acc.w = fmaf(v2, s2.w, acc.w);
        acc.x = fmaf(v3, s3.x, acc.x); acc.y = fmaf(v3, s3.y, acc.y);
        acc.z = fmaf(v3, s3.z, acc.z); acc.w = fmaf(v3, s3.w, acc.w);
    }
    for (; j < end; ++j) {
        int2 e0 = d_epack[j];
        float v0 = __int_as_float(e0.y);
        float4 s0 = *(const float4*)(d_s + (size_t)e0.x * HDIM + t * 4);
        acc.x = fmaf(v0, s0.x, acc.x); acc.y = fmaf(v0, s0.y, acc.y);
        acc.z = fmaf(v0, s0.z, acc.z); acc.w = fmaf(v0, s0.w, acc.w);
    }
    float4 b = *(const float4*)(bias + t * 4);
    float h0 = fmaxf(acc.x + b.x, 0.f);
    float h1 = fmaxf(acc.y + b.y, 0.f);
    float h2 = fmaxf(acc.z + b.z, 0.f);
    float h3 = fmaxf(acc.w + b.w, 0.f);
    __nv_bfloat16 hh0 = __float2bfloat16(h0);
    __nv_bfloat16 hh1 = __float2bfloat16(h1);
    __nv_bfloat16 hh2 = __float2bfloat16(h2);
    __nv_bfloat16 hh3 = __float2bfloat16(h3);
    __nv_bfloat16 ll0 = __float2bfloat16(h0 - __bfloat162float(hh0));
    __nv_bfloat16 ll1 = __float2bfloat16(h1 - __bfloat162float(hh1));
    __nv_bfloat16 ll2 = __float2bfloat16(h2 - __bfloat162float(hh2));
    __nv_bfloat16 ll3 = __float2bfloat16(h3 - __bfloat162float(hh3));
    __nv_bfloat162* H = (__nv_bfloat162*)(d_Ah + (size_t)r * HDIM + t * 4);
    __nv_bfloat162* L = (__nv_bfloat162*)(d_Al + (size_t)r * HDIM + t * 4);
    H[0] = __nv_bfloat162(hh0, hh1);
    H[1] = __nv_bfloat162(hh2, hh3);
    L[0] = __nv_bfloat162(ll0, ll1);
    L[1] = __nv_bfloat162(ll2, ll3);
}

// ---------------- pooling: reads hi/lo (v = hi + lo) ----------------
__global__ __launch_bounds__(256)
void pool_kernel() {
    int f2 = threadIdx.x;               // feature pair 0..255
    const __nv_bfloat162* H = (const __nv_bfloat162*)d_Ah;
    const __nv_bfloat162* L = (const __nv_bfloat162*)d_Al;
    float mx0 = 0.f, mx1 = 0.f, sm0 = 0.f, sm1 = 0.f;
    for (int n = blockIdx.x; n < NNODES; n += gridDim.x) {
        __nv_bfloat162 h = H[(size_t)n * 256 + f2];
        __nv_bfloat162 l = L[(size_t)n * 256 + f2];
        float v0 = __bfloat162float(h.x) + __bfloat162float(l.x);
        float v1 = __bfloat162float(h.y) + __bfloat162float(l.y);
        mx0 = fmaxf(mx0, v0); sm0 += v0;
        mx1 = fmaxf(mx1, v1); sm1 += v1;
    }
    atomicMax(&d_gmax[2 * f2],     __float_as_uint(mx0));   // valid: values >= 0
    atomicMax(&d_gmax[2 * f2 + 1], __float_as_uint(mx1));
    atomicAdd(&d_gsum[2 * f2],     sm0);
    atomicAdd(&d_gsum[2 * f2 + 1], sm1);
}

__global__ void combine_kernel() {
    int f = threadIdx.x;
    d_g[f]       += __uint_as_float(d_gmax[f]);
    d_g[512 + f] += d_gsum[f] * (1.0f / (float)NNODES);
    d_gmax[f] = 0u;
    d_gsum[f] = 0.0f;
}

// ---------------- MLP head + log_softmax ----------------
__global__ __launch_bounds__(128)
void head_kernel(const float* __restrict__ l1W, const float* __restrict__ l1b,
                 const float* __restrict__ l2W, const float* __restrict__ l2b,
                 const float* __restrict__ l3W, const float* __restrict__ l3b,
                 float* __restrict__ out) {
    __shared__ float y1[128];
    __shared__ float y2[64];
    __shared__ float y3[10];
    int t = threadIdx.x;
    {
        float acc = 0.0f;
        for (int i = 0; i < 1024; i++)
            acc = fmaf(d_g[i], l1W[i * 128 + t], acc);
        y1[t] = fmaxf(acc + l1b[t], 0.0f);
    }
    __syncthreads();
    if (t < 64) {
        float acc = 0.0f;
#pragma unroll 8
        for (int i = 0; i < 128; i++)
            acc = fmaf(y1[i], l2W[i * 64 + t], acc);
        y2[t] = fmaxf(acc + l2b[t], 0.0f);
    }
    __syncthreads();
    if (t < 10) {
        float acc = 0.0f;
#pragma unroll
        for (int i = 0; i < 64; i++)
            acc = fmaf(y2[i], l3W[i * 10 + t], acc);
        y3[t] = acc + l3b[t];
    }
    __syncthreads();
    if (t == 0) {
        float m = -1e30f;
#pragma unroll
        for (int j = 0; j < 10; j++) m = fmaxf(m, y3[j]);
        float s = 0.0f;
#pragma unroll
        for (int j = 0; j < 10; j++) s += expf(y3[j] - m);
        float lse = m + logf(s);
#pragma unroll
        for (int j = 0; j < 10; j++) out[j] = y3[j] - lse;
    }
}

// ---------------- launch ----------------
extern "C" void kernel_launch(void* const* d_in, const int* in_sizes, int n_in,
                              void* d_out, int out_size) {
    const float* x        = (const float*)d_in[0];
    const int*   rows     = (const int*)  d_in[1];
    const int*   cols     = (const int*)  d_in[2];
    const float* adj_vals = (const float*)d_in[3];
    const float* W1 = (const float*)d_in[4];
    const float* b1 = (const float*)d_in[5];
    const float* W2 = (const float*)d_in[6];
    const float* b2 = (const float*)d_in[7];
    const float* W3 = (const float*)d_in[8];
    const float* b3 = (const float*)d_in[9];
    const float* l1W = (const float*)d_in[10];
    const float* l1b = (const float*)d_in[11];
    const float* l2W = (const float*)d_in[12];
    const float* l2b = (const float*)d_in[13];
    const float* l3W = (const float*)d_in[14];
    const float* l3b = (const float*)d_in[15];
    float* out = (float*)d_out;

    float* s_g;  cudaGetSymbolAddress((void**)&s_g,  d_s);
    __nv_bfloat16 *Ah_g, *Al_g, *Wth_g, *Wtl_g;
    cudaGetSymbolAddress((void**)&Ah_g,  d_Ah);
    cudaGetSymbolAddress((void**)&Al_g,  d_Al);
    cudaGetSymbolAddress((void**)&Wth_g, d_Wth);
    cudaGetSymbolAddress((void**)&Wtl_g, d_Wtl);

    static bool attr_set = false;
    if (!attr_set) {
        cudaFuncSetAttribute(gemm_bf16x3_kernel,
                             cudaFuncAttributeMaxDynamicSharedMemorySize, DYN_SMEM);
        attr_set = true;
    }

    const size_t WOFF = (size_t)HDIM * HDIM;

    // init + CSR build + weight prep
    init_kernel<<<(NNODES + 255) / 256, 256>>>();
    hist_kernel<<<(NEDGES + 255) / 256, 256>>>(rows);
    scan_kernel<<<1, 1024>>>();
    scatter_kernel<<<(NEDGES + 255) / 256, 256>>>(rows, cols, adj_vals);
    transconv_kernel<<<dim3(16, 16, 3), dim3(32, 8)>>>(W1, W2, W3);
    convert_hilo_kernel<<<(NNODES * HDIM / 4 + 255) / 256, 256>>>(x, NNODES * HDIM / 4);

    dim3 gemm_grid((NNODES + 127) / 128, HDIM / 128);   // (157, 4)

    // layer 1
    gemm_bf16x3_kernel<<<gemm_grid, 256, DYN_SMEM>>>(Ah_g, Al_g, Wth_g, Wtl_g, s_g, NNODES);
    spmm_relu_kernel<<<NNODES, 128>>>(b1);
    pool_kernel<<<256, 256>>>();
    combine_kernel<<<1, 512>>>();

    // layer 2
    gemm_bf16x3_kernel<<<gemm_grid, 256, DYN_SMEM>>>(Ah_g, Al_g, Wth_g + WOFF, Wtl_g + WOFF, s_g, NNODES);
    spmm_relu_kernel<<<NNODES, 128>>>(b2);
    pool_kernel<<<256, 256>>>();
    combine_kernel<<<1, 512>>>();

    // layer 3
    gemm_bf16x3_kernel<<<gemm_grid, 256, DYN_SMEM>>>(Ah_g, Al_g, Wth_g + 2 * WOFF, Wtl_g + 2 * WOFF, s_g, NNODES);
    spmm_relu_kernel<<<NNODES, 128>>>(b3);
    pool_kernel<<<256, 256>>>();
    combine_kernel<<<1, 512>>>();

    // head
    head_kernel<<<1, 128>>>(l1W, l1b, l2W, l2b, l3W, l3b, out);
}

// round 6
// speedup vs baseline: 1.0491x; 1.0355x over previous
#include <cuda_runtime.h>
#include <cuda_bf16.h>
#include <math.h>
#include <stdint.h>

// Problem constants (fixed by the reference)
#define NNODES 20000
#define NEDGES 320000
#define HDIM   512
#define NPAD   20096            // 157 * 128, padded row count for GEMM tiles

// ---------------- scratch (device globals; no runtime allocation) ----------------
__device__ float           d_s [NNODES * HDIM];       // GEMM output
__device__ __nv_bfloat16   d_Ah[NPAD * HDIM];         // activation hi (bf16), padded
__device__ __nv_bfloat16   d_Al[NPAD * HDIM];         // activation lo (bf16), padded
__device__ __nv_bfloat16   d_Wth[3 * HDIM * HDIM];    // W^T hi (bf16), [N,K], 3 layers
__device__ __nv_bfloat16   d_Wtl[3 * HDIM * HDIM];    // W^T lo
__device__ int      d_counts[NNODES];
__device__ int      d_rowptr[NNODES + 1];
__device__ int      d_rowoff[NNODES];
__device__ int2     d_epack[NEDGES];       // (col, float-bits(val))
__device__ float    d_g[1024];             // accumulated [max | mean] over 3 layers
__device__ unsigned d_gmax[HDIM];
__device__ float    d_gsum[HDIM];

// ================= PTX helpers (generic compute_103-safe) =================
__device__ __forceinline__ uint32_t smem_u32(const void* p) {
    uint32_t a;
    asm("{ .reg .u64 t; cvta.to.shared.u64 t, %1; cvt.u32.u64 %0, t; }" : "=r"(a) : "l"(p));
    return a;
}
__device__ __forceinline__ void cp_async16(uint32_t dst, const void* src) {
    asm volatile("cp.async.cg.shared.global [%0], [%1], 16;" :: "r"(dst), "l"(src));
}
#define CP_COMMIT() asm volatile("cp.async.commit_group;" ::: "memory")
#define CP_WAIT1()  asm volatile("cp.async.wait_group 1;" ::: "memory")

__device__ __forceinline__ void ldsm_x4(uint32_t* r, uint32_t addr) {
    asm volatile("ldmatrix.sync.aligned.m8n8.x4.shared.b16 {%0,%1,%2,%3}, [%4];"
        : "=r"(r[0]), "=r"(r[1]), "=r"(r[2]), "=r"(r[3]) : "r"(addr));
}
__device__ __forceinline__ void mma_bf16(float* c, const uint32_t* a, const uint32_t* b) {
    asm volatile(
        "mma.sync.aligned.m16n8k16.row.col.f32.bf16.bf16.f32 "
        "{%0,%1,%2,%3}, {%4,%5,%6,%7}, {%8,%9}, {%0,%1,%2,%3};"
        : "+f"(c[0]), "+f"(c[1]), "+f"(c[2]), "+f"(c[3])
        : "r"(a[0]), "r"(a[1]), "r"(a[2]), "r"(a[3]), "r"(b[0]), "r"(b[1]));
}

// ---------------- init: zero counters / accumulators ----------------
__global__ void init_kernel() {
    int i = blockIdx.x * blockDim.x + threadIdx.x;
    if (i < NNODES) d_counts[i] = 0;
    if (i < 1024)   d_g[i] = 0.0f;
    if (i < HDIM) { d_gmax[i] = 0u; d_gsum[i] = 0.0f; }
}

// ---------------- CSR build ----------------
__global__ void hist_kernel(const int* __restrict__ rows) {
    int e = blockIdx.x * blockDim.x + threadIdx.x;
    if (e < NEDGES) atomicAdd(&d_counts[rows[e]], 1);
}

// single-block scan over 20000 counts -> rowptr (+ rowoff copy fused)
__global__ void scan_kernel() {
    __shared__ int sums[1024];
    const int CH = 20;
    int t = threadIdx.x;
    int base = t * CH;
    int local[CH];
    int run = 0;
#pragma unroll
    for (int i = 0; i < CH; i++) {
        int idx = base + i;
        int v = (idx < NNODES) ? d_counts[idx] : 0;
        run += v;
        local[i] = run;
    }
    sums[t] = run;
    __syncthreads();
    for (int off = 1; off < 1024; off <<= 1) {
        int v = 0;
        if (t >= off) v = sums[t - off];
        __syncthreads();
        if (t >= off) sums[t] += v;
        __syncthreads();
    }
    int offset = (t > 0) ? sums[t - 1] : 0;
#pragma unroll
    for (int i = 0; i < CH; i++) {
        int idx = base + i;
        if (idx < NNODES) {
            d_rowptr[idx + 1] = offset + local[i];
            d_rowoff[idx] = (i == 0) ? offset : offset + local[i - 1];
        }
    }
    if (t == 0) d_rowptr[0] = 0;
}

__global__ void scatter_kernel(const int* __restrict__ rows,
                               const int* __restrict__ cols,
                               const float* __restrict__ vals) {
    int e = blockIdx.x * blockDim.x + threadIdx.x;
    if (e < NEDGES) {
        int r = rows[e];
        int p = atomicAdd(&d_rowoff[r], 1);
        d_epack[p] = make_int2(cols[e], __float_as_int(vals[e]));
    }
}

// ---------------- fp32 -> bf16 hi/lo split (layer-1 input only) ----------------
__global__ void convert_hilo_kernel(const float* __restrict__ src, int n4) {
    int i = blockIdx.x * blockDim.x + threadIdx.x;
    if (i >= n4) return;
    float4 v = ((const float4*)src)[i];
    __nv_bfloat16 h0 = __float2bfloat16(v.x);
    __nv_bfloat16 h1 = __float2bfloat16(v.y);
    __nv_bfloat16 h2 = __float2bfloat16(v.z);
    __nv_bfloat16 h3 = __float2bfloat16(v.w);
    __nv_bfloat16 l0 = __float2bfloat16(v.x - __bfloat162float(h0));
    __nv_bfloat16 l1 = __float2bfloat16(v.y - __bfloat162float(h1));
    __nv_bfloat16 l2 = __float2bfloat16(v.z - __bfloat162float(h2));
    __nv_bfloat16 l3 = __float2bfloat16(v.w - __bfloat162float(h3));
    ((__nv_bfloat162*)d_Ah)[2 * i]     = __nv_bfloat162(h0, h1);
    ((__nv_bfloat162*)d_Ah)[2 * i + 1] = __nv_bfloat162(h2, h3);
    ((__nv_bfloat162*)d_Al)[2 * i]     = __nv_bfloat162(l0, l1);
    ((__nv_bfloat162*)d_Al)[2 * i + 1] = __nv_bfloat162(l2, l3);
}

// ---------------- W [K,N] -> W^T [N,K] hi/lo, all 3 layers in one launch ----------------
__global__ void transconv_kernel(const float* __restrict__ W1,
                                 const float* __restrict__ W2,
                                 const float* __restrict__ W3) {
    __shared__ float t[32][33];
    const float* W = (blockIdx.z == 0) ? W1 : (blockIdx.z == 1) ? W2 : W3;
    size_t obase = (size_t)blockIdx.z * HDIM * HDIM;
    int bx = blockIdx.x * 32, by = blockIdx.y * 32;
    int x = threadIdx.x, y = threadIdx.y;   // 32 x 8
#pragma unroll
    for (int j = 0; j < 32; j += 8)
        t[y + j][x] = W[(size_t)(by + y + j) * HDIM + bx + x];
    __syncthreads();
#pragma unroll
    for (int j = 0; j < 32; j += 8) {
        float v = t[x][y + j];
        __nv_bfloat16 h = __float2bfloat16(v);
        __nv_bfloat16 l = __float2bfloat16(v - __bfloat162float(h));
        size_t o = obase + (size_t)(bx + y + j) * HDIM + by + x;
        d_Wth[o] = h;
        d_Wtl[o] = l;
    }
}

// ---------------- HMMA bf16x3 GEMM: C[M,512] = A @ B^T ----------------
// Block tile 128x128, BK=64, 2-stage cp.async double buffer, 8 warps (2x4), warp tile 64x32.
#define TILE_B   16384                 // 128 rows x 64 bf16 x 2B (128B rows)
#define STAGE_B  (4 * TILE_B)          // Ah, Al, Bh, Bl
#define DYN_SMEM (2 * STAGE_B)         // 131072

__device__ __forceinline__ void load_tile(uint32_t smem_base,
                                          const __nv_bfloat16* __restrict__ src,
                                          int row_base, int k0, int tid) {
    int row = tid >> 1;
    int c0  = (tid & 1) * 4;
    const __nv_bfloat16* g = src + (size_t)(row_base + row) * HDIM + k0;
    uint32_t sb = smem_base + row * 128;
    int xr = row & 7;
#pragma unroll
    for (int c = c0; c < c0 + 4; ++c)
        cp_async16(sb + ((c ^ xr) << 4), g + c * 8);
}

__global__ __launch_bounds__(256, 1)
void gemm_bf16x3_kernel(const __nv_bfloat16* __restrict__ Ah, const __nv_bfloat16* __restrict__ Al,
                        const __nv_bfloat16* __restrict__ Bh, const __nv_bfloat16* __restrict__ Bl,
                        float* __restrict__ C, int M) {
    extern __shared__ __align__(1024) char dsm[];

    const int tid  = threadIdx.x;
    const int wid  = tid >> 5;
    const int lane = tid & 31;
    const int warp_m = wid >> 2;     // 0..1
    const int warp_n = wid & 3;      // 0..3
    const int block_row = blockIdx.x * 128;
    const int block_col = blockIdx.y * 128;

    uint32_t s_base = smem_u32(dsm);

    float acc[4][4][4];
#pragma unroll
    for (int i = 0; i < 4; i++)
#pragma unroll
        for (int j = 0; j < 4; j++)
#pragma unroll
            for (int q = 0; q < 4; q++) acc[i][j][q] = 0.0f;

    // prologue: stage 0 (k0=0), stage 1 (k0=64)
    {
        uint32_t st = s_base;
        load_tile(st,              Ah, block_row, 0, tid);
        load_tile(st + TILE_B,     Al, block_row, 0, tid);
        load_tile(st + 2 * TILE_B, Bh, block_col, 0, tid);
        load_tile(st + 3 * TILE_B, Bl, block_col, 0, tid);
        CP_COMMIT();
        st = s_base + STAGE_B;
        load_tile(st,              Ah, block_row, 64, tid);
        load_tile(st + TILE_B,     Al, block_row, 64, tid);
        load_tile(st + 2 * TILE_B, Bh, block_col, 64, tid);
        load_tile(st + 3 * TILE_B, Bl, block_col, 64, tid);
        CP_COMMIT();
    }

    // per-lane ldmatrix geometry (row&7 invariant under +16-row steps)
    const int a_row  = warp_m * 64 + (lane & 15);
    const int a_half = lane >> 4;
    const int a_x    = a_row & 7;
    const int b_row  = warp_n * 32 + (lane & 15);
    const int b_half = lane >> 4;
    const int b_x    = b_row & 7;

#pragma unroll 1
    for (int c = 0; c < 8; ++c) {
        CP_WAIT1();
        __syncthreads();
        uint32_t st  = s_base + (uint32_t)(c & 1) * STAGE_B;
        uint32_t sAh = st;
        uint32_t sAl = st + TILE_B;
        uint32_t sBh = st + 2 * TILE_B;
        uint32_t sBl = st + 3 * TILE_B;

#pragma unroll
        for (int kk = 0; kk < 4; ++kk) {
            uint32_t a_chunk_off = (uint32_t)(((2 * kk + a_half) ^ a_x) << 4);
            uint32_t b_chunk_off = (uint32_t)(((2 * kk + b_half) ^ b_x) << 4);
            uint32_t ah[4][4], al[4][4];
#pragma unroll
            for (int i = 0; i < 4; ++i) {
                uint32_t ro = (uint32_t)(a_row + i * 16) * 128 + a_chunk_off;
                ldsm_x4(ah[i], sAh + ro);
                ldsm_x4(al[i], sAl + ro);
            }
            uint32_t bh[4][2], bl[4][2];
#pragma unroll
            for (int p = 0; p < 2; ++p) {
                uint32_t ro = (uint32_t)(b_row + p * 16) * 128 + b_chunk_off;
                uint32_t r[4];
                ldsm_x4(r, sBh + ro);
                bh[2 * p][0] = r[0]; bh[2 * p][1] = r[2];
                bh[2 * p + 1][0] = r[1]; bh[2 * p + 1][1] = r[3];
                ldsm_x4(r, sBl + ro);
                bl[2 * p][0] = r[0]; bl[2 * p][1] = r[2];
                bl[2 * p + 1][0] = r[1]; bl[2 * p + 1][1] = r[3];
            }
#pragma unroll
            for (int i = 0; i < 4; ++i)
#pragma unroll
                for (int j = 0; j < 4; ++j) {
                    mma_bf16(acc[i][j], ah[i], bh[j]);
                    mma_bf16(acc[i][j], ah[i], bl[j]);
                    mma_bf16(acc[i][j], al[i], bh[j]);
                }
        }
        __syncthreads();
        if (c + 2 < 8) {
            uint32_t st2 = s_base + (uint32_t)(c & 1) * STAGE_B;
            int k0 = (c + 2) * 64;
            load_tile(st2,              Ah, block_row, k0, tid);
            load_tile(st2 + TILE_B,     Al, block_row, k0, tid);
            load_tile(st2 + 2 * TILE_B, Bh, block_col, k0, tid);
            load_tile(st2 + 3 * TILE_B, Bl, block_col, k0, tid);
        }
        CP_COMMIT();
    }

    // epilogue: direct fp32 stores
    const int r_in = lane >> 2;
    const int c_in = (lane & 3) * 2;
#pragma unroll
    for (int i = 0; i < 4; ++i) {
        int row0 = block_row + warp_m * 64 + i * 16 + r_in;
#pragma unroll
        for (int j = 0; j < 4; ++j) {
            int col = block_col + warp_n * 32 + j * 8 + c_in;
            if (row0 < M)
                *(float2*)(C + (size_t)row0 * HDIM + col) = make_float2(acc[i][j][0], acc[i][j][1]);
            if (row0 + 8 < M)
                *(float2*)(C + (size_t)(row0 + 8) * HDIM + col) = make_float2(acc[i][j][2], acc[i][j][3]);
        }
    }
}

// ---------------- CSR SpMM + bias + ReLU + hi/lo split (fused epilogue) ----------------
__global__ __launch_bounds__(128)
void spmm_relu_kernel(const float* __restrict__ bias) {
    int r = blockIdx.x;
    int t = threadIdx.x;
    int beg = d_rowptr[r];
    int end = d_rowptr[r + 1];
    float4 acc = make_float4(0.f, 0.f, 0.f, 0.f);
    int j = beg;
    for (; j + 3 < end; j += 4) {
        int2 e0 = d_epack[j],     e1 = d_epack[j + 1];
        int2 e2 = d_epack[j + 2], e3 = d_epack[j + 3];
        float4 s0 = *(const float4*)(d_s + (size_t)e0.x * HDIM + t * 4);
        float4 s1 = *(const float4*)(d_s + (size_t)e1.x * HDIM + t * 4);
        float4 s2 = *(const float4*)(d_s + (size_t)e2.x * HDIM + t * 4);
        float4 s3 = *(const float4*)(d_s + (size_t)e3.x * HDIM + t * 4);
        float v0 = __int_as_float(e0.y), v1 = __int_as_float(e1.y);
        float v2 = __int_as_float(e2.y), v3 = __int_as_float(e3.y);
        acc.x = fmaf(v0, s0.x, acc.x); acc.y = fmaf(v0, s0.y, acc.y);
        acc.z = fmaf(v0, s0.z, acc.z); acc.w = fmaf(v0, s0.w, acc.w);
        acc.x = fmaf(v1, s1.x, acc.x); acc.y = fmaf(v1, s1.y, acc.y);
        acc.z = fmaf(v1, s1.z, acc.z); acc.w = fmaf(v1, s1.w, acc.w);
        acc.x = fmaf(v2, s2.x, acc.x); acc.y = fmaf(v2, s2.y, acc.y);
        acc.z = fmaf(v2, s2.z, acc.z); acc.w = fmaf(v2, s2.w, acc.w);
        acc.x = fmaf(v3, s3.x, acc.x); acc.y = fmaf(v3, s3.y, acc.y);
        acc.z = fmaf(v3, s3.z, acc.z); acc.w = fmaf(v3, s3.w, acc.w);
    }
    for (; j < end; ++j) {
        int2 e0 = d_epack[j];
        float v0 = __int_as_float(e0.y);
        float4 s0 = *(const float4*)(d_s + (size_t)e0.x * HDIM + t * 4);
        acc.x = fmaf(v0, s0.x, acc.x); acc.y = fmaf(v0, s0.y, acc.y);
        acc.z = fmaf(v0, s0.z, acc.z); acc.w = fmaf(v0, s0.w, acc.w);
    }
    float4 b = *(const float4*)(bias + t * 4);
    float h0 = fmaxf(acc.x + b.x, 0.f);
    float h1 = fmaxf(acc.y + b.y, 0.f);
    float h2 = fmaxf(acc.z + b.z, 0.f);
    float h3 = fmaxf(acc.w + b.w, 0.f);
    __nv_bfloat16 hh0 = __float2bfloat16(h0);
    __nv_bfloat16 hh1 = __float2bfloat16(h1);
    __nv_bfloat16 hh2 = __float2bfloat16(h2);
    __nv_bfloat16 hh3 = __float2bfloat16(h3);
    __nv_bfloat16 ll0 = __float2bfloat16(h0 - __bfloat162float(hh0));
    __nv_bfloat16 ll1 = __float2bfloat16(h1 - __bfloat162float(hh1));
    __nv_bfloat16 ll2 = __float2bfloat16(h2 - __bfloat162float(hh2));
    __nv_bfloat16 ll3 = __float2bfloat16(h3 - __bfloat162float(hh3));
    __nv_bfloat162* H = (__nv_bfloat162*)(d_Ah + (size_t)r * HDIM + t * 4);
    __nv_bfloat162* L = (__nv_bfloat162*)(d_Al + (size_t)r * HDIM + t * 4);
    H[0] = __nv_bfloat162(hh0, hh1);
    H[1] = __nv_bfloat162(hh2, hh3);
    L[0] = __nv_bfloat162(ll0, ll1);
    L[1] = __nv_bfloat162(ll2, ll3);
}

// ---------------- pooling: reads hi/lo (v = hi + lo) ----------------
__global__ __launch_bounds__(256)
void pool_kernel() {
    int f2 = threadIdx.x;               // feature pair 0..255
    const __nv_bfloat162* H = (const __nv_bfloat162*)d_Ah;
    const __nv_bfloat162* L = (const __nv_bfloat162*)d_Al;
    float mx0 = 0.f, mx1 = 0.f, sm0 = 0.f, sm1 = 0.f;
    for (int n = blockIdx.x; n < NNODES; n += gridDim.x) {
        __nv_bfloat162 h = H[(size_t)n * 256 + f2];
        __nv_bfloat162 l = L[(size_t)n * 256 + f2];
        float v0 = __bfloat162float(h.x) + __bfloat162float(l.x);
        float v1 = __bfloat162float(h.y) + __bfloat162float(l.y);
        mx0 = fmaxf(mx0, v0); sm0 += v0;
        mx1 = fmaxf(mx1, v1); sm1 += v1;
    }
    atomicMax(&d_gmax[2 * f2],     __float_as_uint(mx0));   // valid: values >= 0
    atomicMax(&d_gmax[2 * f2 + 1], __float_as_uint(mx1));
    atomicAdd(&d_gsum[2 * f2],     sm0);
    atomicAdd(&d_gsum[2 * f2 + 1], sm1);
}

__global__ void combine_kernel() {
    int f = threadIdx.x;
    d_g[f]       += __uint_as_float(d_gmax[f]);
    d_g[512 + f] += d_gsum[f] * (1.0f / (float)NNODES);
    d_gmax[f] = 0u;
    d_gsum[f] = 0.0f;
}

// ---------------- MLP head + log_softmax ----------------
__global__ __launch_bounds__(128)
void head_kernel(const float* __restrict__ l1W, const float* __restrict__ l1b,
                 const float* __restrict__ l2W, const float* __restrict__ l2b,
                 const float* __restrict__ l3W, const float* __restrict__ l3b,
                 float* __restrict__ out) {
    __shared__ float y1[128];
    __shared__ float y2[64];
    __shared__ float y3[10];
    int t = threadIdx.x;
    {
        float acc = 0.0f;
        for (int i = 0; i < 1024; i++)
            acc = fmaf(d_g[i], l1W[i * 128 + t], acc);
        y1[t] = fmaxf(acc + l1b[t], 0.0f);
    }
    __syncthreads();
    if (t < 64) {
        float acc = 0.0f;
#pragma unroll 8
        for (int i = 0; i < 128; i++)
            acc = fmaf(y1[i], l2W[i * 64 + t], acc);
        y2[t] = fmaxf(acc + l2b[t], 0.0f);
    }
    __syncthreads();
    if (t < 10) {
        float acc = 0.0f;
#pragma unroll
        for (int i = 0; i < 64; i++)
            acc = fmaf(y2[i], l3W[i * 10 + t], acc);
        y3[t] = acc + l3b[t];
    }
    __syncthreads();
    if (t == 0) {
        float m = -1e30f;
#pragma unroll
        for (int j = 0; j < 10; j++) m = fmaxf(m, y3[j]);
        float s = 0.0f;
#pragma unroll
        for (int j = 0; j < 10; j++) s += expf(y3[j] - m);
        float lse = m + logf(s);
#pragma unroll
        for (int j = 0; j < 10; j++) out[j] = y3[j] - lse;
    }
}

// ---------------- launch (multi-stream fork/join under graph capture) ----------------
extern "C" void kernel_launch(void* const* d_in, const int* in_sizes, int n_in,
                              void* d_out, int out_size) {
    const float* x        = (const float*)d_in[0];
    const int*   rows     = (const int*)  d_in[1];
    const int*   cols     = (const int*)  d_in[2];
    const float* adj_vals = (const float*)d_in[3];
    const float* W1 = (const float*)d_in[4];
    const float* b1 = (const float*)d_in[5];
    const float* W2 = (const float*)d_in[6];
    const float* b2 = (const float*)d_in[7];
    const float* W3 = (const float*)d_in[8];
    const float* b3 = (const float*)d_in[9];
    const float* l1W = (const float*)d_in[10];
    const float* l1b = (const float*)d_in[11];
    const float* l2W = (const float*)d_in[12];
    const float* l2b = (const float*)d_in[13];
    const float* l3W = (const float*)d_in[14];
    const float* l3b = (const float*)d_in[15];
    float* out = (float*)d_out;

    float* s_g;  cudaGetSymbolAddress((void**)&s_g,  d_s);
    __nv_bfloat16 *Ah_g, *Al_g, *Wth_g, *Wtl_g;
    cudaGetSymbolAddress((void**)&Ah_g,  d_Ah);
    cudaGetSymbolAddress((void**)&Al_g,  d_Al);
    cudaGetSymbolAddress((void**)&Wth_g, d_Wth);
    cudaGetSymbolAddress((void**)&Wtl_g, d_Wtl);

    // one-time host-object setup (streams/events are not device memory)
    static bool once = false;
    static cudaStream_t sCSR, sPool;
    static cudaEvent_t evCSR, evSpmm[3], evPool[3], evDone;
    if (!once) {
        cudaFuncSetAttribute(gemm_bf16x3_kernel,
                             cudaFuncAttributeMaxDynamicSharedMemorySize, DYN_SMEM);
        cudaStreamCreateWithFlags(&sCSR,  cudaStreamNonBlocking);
        cudaStreamCreateWithFlags(&sPool, cudaStreamNonBlocking);
        cudaEventCreateWithFlags(&evCSR,  cudaEventDisableTiming);
        cudaEventCreateWithFlags(&evDone, cudaEventDisableTiming);
        for (int i = 0; i < 3; i++) {
            cudaEventCreateWithFlags(&evSpmm[i], cudaEventDisableTiming);
            cudaEventCreateWithFlags(&evPool[i], cudaEventDisableTiming);
        }
        once = true;
    }

    const size_t WOFF = (size_t)HDIM * HDIM;
    const float* Wb[3] = {W1, W2, W3};
    const float* bb[3] = {b1, b2, b3};
    cudaStream_t s0 = 0;   // capture-origin (default) stream

    // fork: CSR side stream must branch FROM the capture stream
    cudaEventRecord(evDone, s0);               // reuse evDone as the fork event
    cudaStreamWaitEvent(sCSR, evDone, 0);
    cudaStreamWaitEvent(sPool, evDone, 0);

    // side stream: init + CSR build (independent of GEMM1 inputs)
    init_kernel<<<(NNODES + 255) / 256, 256, 0, sCSR>>>();
    hist_kernel<<<(NEDGES + 255) / 256, 256, 0, sCSR>>>(rows);
    scan_kernel<<<1, 1024, 0, sCSR>>>();
    scatter_kernel<<<(NEDGES + 255) / 256, 256, 0, sCSR>>>(rows, cols, adj_vals);
    cudaEventRecord(evCSR, sCSR);

    // main stream: weight prep + layer-1 input conversion
    transconv_kernel<<<dim3(16, 16, 3), dim3(32, 8), 0, s0>>>(W1, W2, W3);
    convert_hilo_kernel<<<(NNODES * HDIM / 4 + 255) / 256, 256, 0, s0>>>(x, NNODES * HDIM / 4);

    dim3 gemm_grid((NNODES + 127) / 128, HDIM / 128);   // (157, 4)

    for (int L = 0; L < 3; ++L) {
        gemm_bf16x3_kernel<<<gemm_grid, 256, DYN_SMEM, s0>>>(
            Ah_g, Al_g, Wth_g + L * WOFF, Wtl_g + L * WOFF, s_g, NNODES);
        if (L == 0) cudaStreamWaitEvent(s0, evCSR, 0);          // CSR ready before SpMM1
        else        cudaStreamWaitEvent(s0, evPool[L - 1], 0);  // pool(L-1) done reading d_Ah
        spmm_relu_kernel<<<NNODES, 128, 0, s0>>>(bb[L]);
        cudaEventRecord(evSpmm[L], s0);

        // pool + combine on side stream, overlapped with next GEMM
        cudaStreamWaitEvent(sPool, evSpmm[L], 0);
        pool_kernel<<<256, 256, 0, sPool>>>();
        cudaEventRecord(evPool[L], sPool);
        combine_kernel<<<1, 512, 0, sPool>>>();
    }

    // join: head needs combine3 (d_g complete)
    cudaEventRecord(evDone, sPool);
    cudaStreamWaitEvent(s0, evDone, 0);
    head_kernel<<<1, 128, 0, s0>>>(l1W, l1b, l2W, l2b, l3W, l3b, out);
}

// round 7
// speedup vs baseline: 1.3193x; 1.2575x over previous
#include <cuda_runtime.h>
#include <cuda_fp16.h>
#include <math.h>
#include <stdint.h>

// Problem constants (fixed by the reference)
#define NNODES 20000
#define NEDGES 320000
#define HDIM   512
#define NPAD   20096            // 157 * 128, padded row count for GEMM tiles

// ---------------- scratch (device globals; no runtime allocation) ----------------
__device__ float    d_s [NNODES * HDIM];       // GEMM output
__device__ __half   d_Ah[NPAD * HDIM];         // activation hi (fp16), padded
__device__ __half   d_Al[NPAD * HDIM];         // activation lo (fp16), padded
__device__ __half   d_Wh[3 * HDIM * HDIM];     // W^T (fp16), [N,K] layout, 3 layers
__device__ int      d_counts[NNODES];
__device__ int      d_rowptr[NNODES + 1];
__device__ int      d_rowoff[NNODES];
__device__ int2     d_epack[NEDGES];       // (col, float-bits(val))
__device__ float    d_g[1024];             // accumulated [max | mean] over 3 layers
__device__ unsigned d_gmax[HDIM];
__device__ float    d_gsum[HDIM];

// ================= PTX helpers (generic compute_103-safe) =================
__device__ __forceinline__ uint32_t smem_u32(const void* p) {
    uint32_t a;
    asm("{ .reg .u64 t; cvta.to.shared.u64 t, %1; cvt.u32.u64 %0, t; }" : "=r"(a) : "l"(p));
    return a;
}
__device__ __forceinline__ void cp_async16(uint32_t dst, const void* src) {
    asm volatile("cp.async.cg.shared.global [%0], [%1], 16;" :: "r"(dst), "l"(src));
}
#define CP_COMMIT() asm volatile("cp.async.commit_group;" ::: "memory")
#define CP_WAIT1()  asm volatile("cp.async.wait_group 1;" ::: "memory")

__device__ __forceinline__ void ldsm_x4(uint32_t* r, uint32_t addr) {
    asm volatile("ldmatrix.sync.aligned.m8n8.x4.shared.b16 {%0,%1,%2,%3}, [%4];"
        : "=r"(r[0]), "=r"(r[1]), "=r"(r[2]), "=r"(r[3]) : "r"(addr));
}
__device__ __forceinline__ void mma_f16(float* c, const uint32_t* a, const uint32_t* b) {
    asm volatile(
        "mma.sync.aligned.m16n8k16.row.col.f32.f16.f16.f32 "
        "{%0,%1,%2,%3}, {%4,%5,%6,%7}, {%8,%9}, {%0,%1,%2,%3};"
        : "+f"(c[0]), "+f"(c[1]), "+f"(c[2]), "+f"(c[3])
        : "r"(a[0]), "r"(a[1]), "r"(a[2]), "r"(a[3]), "r"(b[0]), "r"(b[1]));
}

// ---------------- init: zero counters / accumulators ----------------
__global__ void init_kernel() {
    int i = blockIdx.x * blockDim.x + threadIdx.x;
    if (i < NNODES) d_counts[i] = 0;
    if (i < 1024)   d_g[i] = 0.0f;
    if (i < HDIM) { d_gmax[i] = 0u; d_gsum[i] = 0.0f; }
}

// ---------------- CSR build ----------------
__global__ void hist_kernel(const int* __restrict__ rows) {
    int e = blockIdx.x * blockDim.x + threadIdx.x;
    if (e < NEDGES) atomicAdd(&d_counts[rows[e]], 1);
}

// single-block scan over 20000 counts -> rowptr (+ rowoff copy fused)
__global__ void scan_kernel() {
    __shared__ int sums[1024];
    const int CH = 20;
    int t = threadIdx.x;
    int base = t * CH;
    int local[CH];
    int run = 0;
#pragma unroll
    for (int i = 0; i < CH; i++) {
        int idx = base + i;
        int v = (idx < NNODES) ? d_counts[idx] : 0;
        run += v;
        local[i] = run;
    }
    sums[t] = run;
    __syncthreads();
    for (int off = 1; off < 1024; off <<= 1) {
        int v = 0;
        if (t >= off) v = sums[t - off];
        __syncthreads();
        if (t >= off) sums[t] += v;
        __syncthreads();
    }
    int offset = (t > 0) ? sums[t - 1] : 0;
#pragma unroll
    for (int i = 0; i < CH; i++) {
        int idx = base + i;
        if (idx < NNODES) {
            d_rowptr[idx + 1] = offset + local[i];
            d_rowoff[idx] = (i == 0) ? offset : offset + local[i - 1];
        }
    }
    if (t == 0) d_rowptr[0] = 0;
}

__global__ void scatter_kernel(const int* __restrict__ rows,
                               const int* __restrict__ cols,
                               const float* __restrict__ vals) {
    int e = blockIdx.x * blockDim.x + threadIdx.x;
    if (e < NEDGES) {
        int r = rows[e];
        int p = atomicAdd(&d_rowoff[r], 1);
        d_epack[p] = make_int2(cols[e], __float_as_int(vals[e]));
    }
}

// ---------------- fp32 -> fp16 hi/lo split (layer-1 input only) ----------------
__global__ void convert_hilo_kernel(const float* __restrict__ src, int n4) {
    int i = blockIdx.x * blockDim.x + threadIdx.x;
    if (i >= n4) return;
    float4 v = ((const float4*)src)[i];
    __half h0 = __float2half_rn(v.x);
    __half h1 = __float2half_rn(v.y);
    __half h2 = __float2half_rn(v.z);
    __half h3 = __float2half_rn(v.w);
    __half l0 = __float2half_rn(v.x - __half2float(h0));
    __half l1 = __float2half_rn(v.y - __half2float(h1));
    __half l2 = __float2half_rn(v.z - __half2float(h2));
    __half l3 = __float2half_rn(v.w - __half2float(h3));
    ((__half2*)d_Ah)[2 * i]     = __halves2half2(h0, h1);
    ((__half2*)d_Ah)[2 * i + 1] = __halves2half2(h2, h3);
    ((__half2*)d_Al)[2 * i]     = __halves2half2(l0, l1);
    ((__half2*)d_Al)[2 * i + 1] = __halves2half2(l2, l3);
}

// ---------------- W [K,N] -> W^T [N,K] fp16, all 3 layers in one launch ----------------
__global__ void transconv_kernel(const float* __restrict__ W1,
                                 const float* __restrict__ W2,
                                 const float* __restrict__ W3) {
    __shared__ float t[32][33];
    const float* W = (blockIdx.z == 0) ? W1 : (blockIdx.z == 1) ? W2 : W3;
    size_t obase = (size_t)blockIdx.z * HDIM * HDIM;
    int bx = blockIdx.x * 32, by = blockIdx.y * 32;
    int x = threadIdx.x, y = threadIdx.y;   // 32 x 8
#pragma unroll
    for (int j = 0; j < 32; j += 8)
        t[y + j][x] = W[(size_t)(by + y + j) * HDIM + bx + x];
    __syncthreads();
#pragma unroll
    for (int j = 0; j < 32; j += 8) {
        size_t o = obase + (size_t)(bx + y + j) * HDIM + by + x;
        d_Wh[o] = __float2half_rn(t[x][y + j]);
    }
}

// ---------------- HMMA fp16x2 GEMM: C[M,512] = (Ah+Al) @ Bh^T ----------------
// Block tile 128x128, BK=64, 2-stage cp.async double buffer, 8 warps (2x4), warp tile 64x32.
// 3 tiles/stage (Ah, Al, Bh) -> 96KB/CTA -> 2 CTAs/SM.
#define TILE_B   16384                 // 128 rows x 64 fp16 x 2B (128B rows)
#define STAGE_B  (3 * TILE_B)          // Ah, Al, Bh
#define DYN_SMEM (2 * STAGE_B)         // 98304

__device__ __forceinline__ void load_tile(uint32_t smem_base,
                                          const __half* __restrict__ src,
                                          int row_base, int k0, int tid) {
    int row = tid >> 1;
    int c0  = (tid & 1) * 4;
    const __half* g = src + (size_t)(row_base + row) * HDIM + k0;
    uint32_t sb = smem_base + row * 128;
    int xr = row & 7;
#pragma unroll
    for (int c = c0; c < c0 + 4; ++c)
        cp_async16(sb + ((c ^ xr) << 4), g + c * 8);
}

__global__ __launch_bounds__(256, 2)
void gemm_f16x2_kernel(const __half* __restrict__ Ah, const __half* __restrict__ Al,
                       const __half* __restrict__ Bh,
                       float* __restrict__ C, int M) {
    extern __shared__ __align__(1024) char dsm[];

    const int tid  = threadIdx.x;
    const int wid  = tid >> 5;
    const int lane = tid & 31;
    const int warp_m = wid >> 2;     // 0..1
    const int warp_n = wid & 3;      // 0..3
    const int block_row = blockIdx.x * 128;
    const int block_col = blockIdx.y * 128;

    uint32_t s_base = smem_u32(dsm);

    float acc[4][4][4];
#pragma unroll
    for (int i = 0; i < 4; i++)
#pragma unroll
        for (int j = 0; j < 4; j++)
#pragma unroll
            for (int q = 0; q < 4; q++) acc[i][j][q] = 0.0f;

    // prologue: stage 0 (k0=0), stage 1 (k0=64)
    {
        uint32_t st = s_base;
        load_tile(st,              Ah, block_row, 0, tid);
        load_tile(st + TILE_B,     Al, block_row, 0, tid);
        load_tile(st + 2 * TILE_B, Bh, block_col, 0, tid);
        CP_COMMIT();
        st = s_base + STAGE_B;
        load_tile(st,              Ah, block_row, 64, tid);
        load_tile(st + TILE_B,     Al, block_row, 64, tid);
        load_tile(st + 2 * TILE_B, Bh, block_col, 64, tid);
        CP_COMMIT();
    }

    // per-lane ldmatrix geometry (row&7 invariant under +16-row steps)
    const int a_row  = warp_m * 64 + (lane & 15);
    const int a_half = lane >> 4;
    const int a_x    = a_row & 7;
    const int b_row  = warp_n * 32 + (lane & 15);
    const int b_half = lane >> 4;
    const int b_x    = b_row & 7;

#pragma unroll 1
    for (int c = 0; c < 8; ++c) {
        CP_WAIT1();
        __syncthreads();
        uint32_t st  = s_base + (uint32_t)(c & 1) * STAGE_B;
        uint32_t sAh = st;
        uint32_t sAl = st + TILE_B;
        uint32_t sBh = st + 2 * TILE_B;

#pragma unroll
        for (int kk = 0; kk < 4; ++kk) {
            uint32_t a_chunk_off = (uint32_t)(((2 * kk + a_half) ^ a_x) << 4);
            uint32_t b_chunk_off = (uint32_t)(((2 * kk + b_half) ^ b_x) << 4);
            uint32_t ah[4][4], al[4][4];
#pragma unroll
            for (int i = 0; i < 4; ++i) {
                uint32_t ro = (uint32_t)(a_row + i * 16) * 128 + a_chunk_off;
                ldsm_x4(ah[i], sAh + ro);
                ldsm_x4(al[i], sAl + ro);
            }
            uint32_t bh[4][2];
#pragma unroll
            for (int p = 0; p < 2; ++p) {
                uint32_t ro = (uint32_t)(b_row + p * 16) * 128 + b_chunk_off;
                uint32_t r[4];
                ldsm_x4(r, sBh + ro);
                bh[2 * p][0] = r[0]; bh[2 * p][1] = r[2];
                bh[2 * p + 1][0] = r[1]; bh[2 * p + 1][1] = r[3];
            }
#pragma unroll
            for (int i = 0; i < 4; ++i)
#pragma unroll
                for (int j = 0; j < 4; ++j) {
                    mma_f16(acc[i][j], ah[i], bh[j]);
                    mma_f16(acc[i][j], al[i], bh[j]);
                }
        }
        __syncthreads();
        if (c + 2 < 8) {
            uint32_t st2 = s_base + (uint32_t)(c & 1) * STAGE_B;
            int k0 = (c + 2) * 64;
            load_tile(st2,              Ah, block_row, k0, tid);
            load_tile(st2 + TILE_B,     Al, block_row, k0, tid);
            load_tile(st2 + 2 * TILE_B, Bh, block_col, k0, tid);
        }
        CP_COMMIT();
    }

    // epilogue: direct fp32 stores
    const int r_in = lane >> 2;
    const int c_in = (lane & 3) * 2;
#pragma unroll
    for (int i = 0; i < 4; ++i) {
        int row0 = block_row + warp_m * 64 + i * 16 + r_in;
#pragma unroll
        for (int j = 0; j < 4; ++j) {
            int col = block_col + warp_n * 32 + j * 8 + c_in;
            if (row0 < M)
                *(float2*)(C + (size_t)row0 * HDIM + col) = make_float2(acc[i][j][0], acc[i][j][1]);
            if (row0 + 8 < M)
                *(float2*)(C + (size_t)(row0 + 8) * HDIM + col) = make_float2(acc[i][j][2], acc[i][j][3]);
        }
    }
}

// ---------------- CSR SpMM + bias + ReLU + fp16 hi/lo split (fused epilogue) ----------------
__global__ __launch_bounds__(128)
void spmm_relu_kernel(const float* __restrict__ bias) {
    int r = blockIdx.x;
    int t = threadIdx.x;
    int beg = d_rowptr[r];
    int end = d_rowptr[r + 1];
    float4 acc = make_float4(0.f, 0.f, 0.f, 0.f);
    int j = beg;
    for (; j + 3 < end; j += 4) {
        int2 e0 = d_epack[j],     e1 = d_epack[j + 1];
        int2 e2 = d_epack[j + 2], e3 = d_epack[j + 3];
        float4 s0 = *(const float4*)(d_s + (size_t)e0.x * HDIM + t * 4);
        float4 s1 = *(const float4*)(d_s + (size_t)e1.x * HDIM + t * 4);
        float4 s2 = *(const float4*)(d_s + (size_t)e2.x * HDIM + t * 4);
        float4 s3 = *(const float4*)(d_s + (size_t)e3.x * HDIM + t * 4);
        float v0 = __int_as_float(e0.y), v1 = __int_as_float(e1.y);
        float v2 = __int_as_float(e2.y), v3 = __int_as_float(e3.y);
        acc.x = fmaf(v0, s0.x, acc.x); acc.y = fmaf(v0, s0.y, acc.y);
        acc.z = fmaf(v0, s0.z, acc.z); acc.w = fmaf(v0, s0.w, acc.w);
        acc.x = fmaf(v1, s1.x, acc.x); acc.y = fmaf(v1, s1.y, acc.y);
        acc.z = fmaf(v1, s1.z, acc.z); acc.w = fmaf(v1, s1.w, acc.w);
        acc.x = fmaf(v2, s2.x, acc.x); acc.y = fmaf(v2, s2.y, acc.y);
        acc.z = fmaf(v2, s2.z, acc.z); acc.w = fmaf(v2, s2.w, acc.w);
        acc.x = fmaf(v3, s3.x, acc.x); acc.y = fmaf(v3, s3.y, acc.y);
        acc.z = fmaf(v3, s3.z, acc.z); acc.w = fmaf(v3, s3.w, acc.w);
    }
    for (; j < end; ++j) {
        int2 e0 = d_epack[j];
        float v0 = __int_as_float(e0.y);
        float4 s0 = *(const float4*)(d_s + (size_t)e0.x * HDIM + t * 4);
        acc.x = fmaf(v0, s0.x, acc.x); acc.y = fmaf(v0, s0.y, acc.y);
        acc.z = fmaf(v0, s0.z, acc.z); acc.w = fmaf(v0, s0.w, acc.w);
    }
    float4 b = *(const float4*)(bias + t * 4);
    float h0 = fmaxf(acc.x + b.x, 0.f);
    float h1 = fmaxf(acc.y + b.y, 0.f);
    float h2 = fmaxf(acc.z + b.z, 0.f);
    float h3 = fmaxf(acc.w + b.w, 0.f);
    __half hh0 = __float2half_rn(h0);
    __half hh1 = __float2half_rn(h1);
    __half hh2 = __float2half_rn(h2);
    __half hh3 = __float2half_rn(h3);
    __half ll0 = __float2half_rn(h0 - __half2float(hh0));
    __half ll1 = __float2half_rn(h1 - __half2float(hh1));
    __half ll2 = __float2half_rn(h2 - __half2float(hh2));
    __half ll3 = __float2half_rn(h3 - __half2float(hh3));
    __half2* H = (__half2*)(d_Ah + (size_t)r * HDIM + t * 4);
    __half2* L = (__half2*)(d_Al + (size_t)r * HDIM + t * 4);
    H[0] = __halves2half2(hh0, hh1);
    H[1] = __halves2half2(hh2, hh3);
    L[0] = __halves2half2(ll0, ll1);
    L[1] = __halves2half2(ll2, ll3);
}

// ---------------- pooling: reads hi/lo (v = hi + lo) ----------------
__global__ __launch_bounds__(256)
void pool_kernel() {
    int f2 = threadIdx.x;               // feature pair 0..255
    const __half2* H = (const __half2*)d_Ah;
    const __half2* L = (const __half2*)d_Al;
    float mx0 = 0.f, mx1 = 0.f, sm0 = 0.f, sm1 = 0.f;
    for (int n = blockIdx.x; n < NNODES; n += gridDim.x) {
        __half2 h = H[(size_t)n * 256 + f2];
        __half2 l = L[(size_t)n * 256 + f2];
        float v0 = __half2float(h.x) + __half2float(l.x);
        float v1 = __half2float(h.y) + __half2float(l.y);
        mx0 = fmaxf(mx0, v0); sm0 += v0;
        mx1 = fmaxf(mx1, v1); sm1 += v1;
    }
    atomicMax(&d_gmax[2 * f2],     __float_as_uint(mx0));   // valid: values >= 0
    atomicMax(&d_gmax[2 * f2 + 1], __float_as_uint(mx1));
    atomicAdd(&d_gsum[2 * f2],     sm0);
    atomicAdd(&d_gsum[2 * f2 + 1], sm1);
}

__global__ void combine_kernel() {
    int f = threadIdx.x;
    d_g[f]       += __uint_as_float(d_gmax[f]);
    d_g[512 + f] += d_gsum[f] * (1.0f / (float)NNODES);
    d_gmax[f] = 0u;
    d_gsum[f] = 0.0f;
}

// ---------------- MLP head + log_softmax ----------------
__global__ __launch_bounds__(128)
void head_kernel(const float* __restrict__ l1W, const float* __restrict__ l1b,
                 const float* __restrict__ l2W, const float* __restrict__ l2b,
                 const float* __restrict__ l3W, const float* __restrict__ l3b,
                 float* __restrict__ out) {
    __shared__ float y1[128];
    __shared__ float y2[64];
    __shared__ float y3[10];
    int t = threadIdx.x;
    {
        float acc = 0.0f;
        for (int i = 0; i < 1024; i++)
            acc = fmaf(d_g[i], l1W[i * 128 + t], acc);
        y1[t] = fmaxf(acc + l1b[t], 0.0f);
    }
    __syncthreads();
    if (t < 64) {
        float acc = 0.0f;
#pragma unroll 8
        for (int i = 0; i < 128; i++)
            acc = fmaf(y1[i], l2W[i * 64 + t], acc);
        y2[t] = fmaxf(acc + l2b[t], 0.0f);
    }
    __syncthreads();
    if (t < 10) {
        float acc = 0.0f;
#pragma unroll
        for (int i = 0; i < 64; i++)
            acc = fmaf(y2[i], l3W[i * 10 + t], acc);
        y3[t] = acc + l3b[t];
    }
    __syncthreads();
    if (t == 0) {
        float m = -1e30f;
#pragma unroll
        for (int j = 0; j < 10; j++) m = fmaxf(m, y3[j]);
        float s = 0.0f;
#pragma unroll
        for (int j = 0; j < 10; j++) s += expf(y3[j] - m);
        float lse = m + logf(s);
#pragma unroll
        for (int j = 0; j < 10; j++) out[j] = y3[j] - lse;
    }
}

// ---------------- launch (multi-stream fork/join under graph capture) ----------------
extern "C" void kernel_launch(void* const* d_in, const int* in_sizes, int n_in,
                              void* d_out, int out_size) {
    const float* x        = (const float*)d_in[0];
    const int*   rows     = (const int*)  d_in[1];
    const int*   cols     = (const int*)  d_in[2];
    const float* adj_vals = (const float*)d_in[3];
    const float* W1 = (const float*)d_in[4];
    const float* b1 = (const float*)d_in[5];
    const float* W2 = (const float*)d_in[6];
    const float* b2 = (const float*)d_in[7];
    const float* W3 = (const float*)d_in[8];
    const float* b3 = (const float*)d_in[9];
    const float* l1W = (const float*)d_in[10];
    const float* l1b = (const float*)d_in[11];
    const float* l2W = (const float*)d_in[12];
    const float* l2b = (const float*)d_in[13];
    const float* l3W = (const float*)d_in[14];
    const float* l3b = (const float*)d_in[15];
    float* out = (float*)d_out;

    float* s_g;  cudaGetSymbolAddress((void**)&s_g,  d_s);
    __half *Ah_g, *Al_g, *Wh_g;
    cudaGetSymbolAddress((void**)&Ah_g, d_Ah);
    cudaGetSymbolAddress((void**)&Al_g, d_Al);
    cudaGetSymbolAddress((void**)&Wh_g, d_Wh);

    // one-time host-object setup (streams/events are not device memory)
    static bool once = false;
    static cudaStream_t sCSR, sPool;
    static cudaEvent_t evFork, evCSR, evSpmm[3], evPool[3], evDone;
    if (!once) {
        cudaFuncSetAttribute(gemm_f16x2_kernel,
                             cudaFuncAttributeMaxDynamicSharedMemorySize, DYN_SMEM);
        cudaStreamCreateWithFlags(&sCSR,  cudaStreamNonBlocking);
        cudaStreamCreateWithFlags(&sPool, cudaStreamNonBlocking);
        cudaEventCreateWithFlags(&evFork, cudaEventDisableTiming);
        cudaEventCreateWithFlags(&evCSR,  cudaEventDisableTiming);
        cudaEventCreateWithFlags(&evDone, cudaEventDisableTiming);
        for (int i = 0; i < 3; i++) {
            cudaEventCreateWithFlags(&evSpmm[i], cudaEventDisableTiming);
            cudaEventCreateWithFlags(&evPool[i], cudaEventDisableTiming);
        }
        once = true;
    }

    const size_t WOFF = (size_t)HDIM * HDIM;
    const float* bb[3] = {b1, b2, b3};
    cudaStream_t s0 = 0;   // capture-origin (default) stream

    // fork side streams from capture stream
    cudaEventRecord(evFork, s0);
    cudaStreamWaitEvent(sCSR, evFork, 0);
    cudaStreamWaitEvent(sPool, evFork, 0);

    dim3 gemm_grid((NNODES + 127) / 128, HDIM / 128);   // (157, 4)

    // main stream first (launch-order: 1 transconv, 2 convert) so GEMM lands at slot 6 for ncu
    transconv_kernel<<<dim3(16, 16, 3), dim3(32, 8), 0, s0>>>(W1, W2, W3);
    convert_hilo_kernel<<<(NNODES * HDIM / 4 + 255) / 256, 256, 0, s0>>>(x, NNODES * HDIM / 4);

    // side stream: CSR prefix (3 init, 4 hist, 5 scan)
    init_kernel<<<(NNODES + 255) / 256, 256, 0, sCSR>>>();
    hist_kernel<<<(NEDGES + 255) / 256, 256, 0, sCSR>>>(rows);
    scan_kernel<<<1, 1024, 0, sCSR>>>();

    // 6: layer-1 GEMM (ncu -s 5 -c 1 should capture this one)
    gemm_f16x2_kernel<<<gemm_grid, 256, DYN_SMEM, s0>>>(Ah_g, Al_g, Wh_g, s_g, NNODES);

    // 7: scatter (side stream), then CSR-complete event
    scatter_kernel<<<(NEDGES + 255) / 256, 256, 0, sCSR>>>(rows, cols, adj_vals);
    cudaEventRecord(evCSR, sCSR);

    for (int L = 0; L < 3; ++L) {
        if (L > 0)
            gemm_f16x2_kernel<<<gemm_grid, 256, DYN_SMEM, s0>>>(
                Ah_g, Al_g, Wh_g + L * WOFF, s_g, NNODES);
        if (L == 0) cudaStreamWaitEvent(s0, evCSR, 0);          // CSR ready before SpMM1
        else        cudaStreamWaitEvent(s0, evPool[L - 1], 0);  // pool(L-1) done reading d_Ah
        spmm_relu_kernel<<<NNODES, 128, 0, s0>>>(bb[L]);
        cudaEventRecord(evSpmm[L], s0);

        // pool + combine on side stream, overlapped with next GEMM
        cudaStreamWaitEvent(sPool, evSpmm[L], 0);
        pool_kernel<<<256, 256, 0, sPool>>>();
        cudaEventRecord(evPool[L], sPool);
        combine_kernel<<<1, 512, 0, sPool>>>();
    }

    // join: head needs combine3 (d_g complete)
    cudaEventRecord(evDone, sPool);
    cudaStreamWaitEvent(s0, evDone, 0);
    head_kernel<<<1, 128, 0, s0>>>(l1W, l1b, l2W, l2b, l3W, l3b, out);
}

// round 8
// speedup vs baseline: 1.4553x; 1.1031x over previous
#include <cuda_runtime.h>
#include <cuda_fp16.h>
#include <math.h>
#include <stdint.h>

// Problem constants (fixed by the reference)
#define NNODES 20000
#define NEDGES 320000
#define HDIM   512
#define NPAD   20096            // 157 * 128, padded row count for GEMM tiles

// ---------------- scratch (device globals; no runtime allocation) ----------------
__device__ __half   d_s [NNODES * HDIM];       // GEMM output (fp16)
__device__ __half   d_Ah[NPAD * HDIM];         // activation hi (fp16), padded
__device__ __half   d_Al[NPAD * HDIM];         // activation lo (fp16), padded
__device__ __half   d_Wh[3 * HDIM * HDIM];     // W^T (fp16), [N,K] layout, 3 layers
__device__ int      d_counts[NNODES];
__device__ int      d_rowptr[NNODES + 1];
__device__ int      d_rowoff[NNODES];
__device__ int2     d_epack[NEDGES];       // (col, float-bits(val))
__device__ float    d_g[1024];             // accumulated [max | mean] over 3 layers
__device__ unsigned d_gmax[HDIM];
__device__ float    d_gsum[HDIM];

// ================= PTX helpers (generic compute_103-safe) =================
__device__ __forceinline__ uint32_t smem_u32(const void* p) {
    uint32_t a;
    asm("{ .reg .u64 t; cvta.to.shared.u64 t, %1; cvt.u32.u64 %0, t; }" : "=r"(a) : "l"(p));
    return a;
}
__device__ __forceinline__ void cp_async16(uint32_t dst, const void* src) {
    asm volatile("cp.async.cg.shared.global [%0], [%1], 16;" :: "r"(dst), "l"(src));
}
#define CP_COMMIT() asm volatile("cp.async.commit_group;" ::: "memory")
#define CP_WAIT1()  asm volatile("cp.async.wait_group 1;" ::: "memory")

__device__ __forceinline__ void ldsm_x4(uint32_t* r, uint32_t addr) {
    asm volatile("ldmatrix.sync.aligned.m8n8.x4.shared.b16 {%0,%1,%2,%3}, [%4];"
        : "=r"(r[0]), "=r"(r[1]), "=r"(r[2]), "=r"(r[3]) : "r"(addr));
}
__device__ __forceinline__ void mma_f16(float* c, const uint32_t* a, const uint32_t* b) {
    asm volatile(
        "mma.sync.aligned.m16n8k16.row.col.f32.f16.f16.f32 "
        "{%0,%1,%2,%3}, {%4,%5,%6,%7}, {%8,%9}, {%0,%1,%2,%3};"
        : "+f"(c[0]), "+f"(c[1]), "+f"(c[2]), "+f"(c[3])
        : "r"(a[0]), "r"(a[1]), "r"(a[2]), "r"(a[3]), "r"(b[0]), "r"(b[1]));
}

// ---------------- init: zero counters / accumulators ----------------
__global__ void init_kernel() {
    int i = blockIdx.x * blockDim.x + threadIdx.x;
    if (i < NNODES) d_counts[i] = 0;
    if (i < 1024)   d_g[i] = 0.0f;
    if (i < HDIM) { d_gmax[i] = 0u; d_gsum[i] = 0.0f; }
}

// ---------------- CSR build ----------------
__global__ void hist_kernel(const int* __restrict__ rows) {
    int e = blockIdx.x * blockDim.x + threadIdx.x;
    if (e < NEDGES) atomicAdd(&d_counts[rows[e]], 1);
}

// single-block scan over 20000 counts -> rowptr (+ rowoff copy fused)
__global__ void scan_kernel() {
    __shared__ int sums[1024];
    const int CH = 20;
    int t = threadIdx.x;
    int base = t * CH;
    int local[CH];
    int run = 0;
#pragma unroll
    for (int i = 0; i < CH; i++) {
        int idx = base + i;
        int v = (idx < NNODES) ? d_counts[idx] : 0;
        run += v;
        local[i] = run;
    }
    sums[t] = run;
    __syncthreads();
    for (int off = 1; off < 1024; off <<= 1) {
        int v = 0;
        if (t >= off) v = sums[t - off];
        __syncthreads();
        if (t >= off) sums[t] += v;
        __syncthreads();
    }
    int offset = (t > 0) ? sums[t - 1] : 0;
#pragma unroll
    for (int i = 0; i < CH; i++) {
        int idx = base + i;
        if (idx < NNODES) {
            d_rowptr[idx + 1] = offset + local[i];
            d_rowoff[idx] = (i == 0) ? offset : offset + local[i - 1];
        }
    }
    if (t == 0) d_rowptr[0] = 0;
}

__global__ void scatter_kernel(const int* __restrict__ rows,
                               const int* __restrict__ cols,
                               const float* __restrict__ vals) {
    int e = blockIdx.x * blockDim.x + threadIdx.x;
    if (e < NEDGES) {
        int r = rows[e];
        int p = atomicAdd(&d_rowoff[r], 1);
        d_epack[p] = make_int2(cols[e], __float_as_int(vals[e]));
    }
}

// ---------------- fp32 -> fp16 hi/lo split (layer-1 input only) ----------------
__global__ void convert_hilo_kernel(const float* __restrict__ src, int n4) {
    int i = blockIdx.x * blockDim.x + threadIdx.x;
    if (i >= n4) return;
    float4 v = ((const float4*)src)[i];
    __half h0 = __float2half_rn(v.x);
    __half h1 = __float2half_rn(v.y);
    __half h2 = __float2half_rn(v.z);
    __half h3 = __float2half_rn(v.w);
    __half l0 = __float2half_rn(v.x - __half2float(h0));
    __half l1 = __float2half_rn(v.y - __half2float(h1));
    __half l2 = __float2half_rn(v.z - __half2float(h2));
    __half l3 = __float2half_rn(v.w - __half2float(h3));
    ((__half2*)d_Ah)[2 * i]     = __halves2half2(h0, h1);
    ((__half2*)d_Ah)[2 * i + 1] = __halves2half2(h2, h3);
    ((__half2*)d_Al)[2 * i]     = __halves2half2(l0, l1);
    ((__half2*)d_Al)[2 * i + 1] = __halves2half2(l2, l3);
}

// ---------------- W [K,N] -> W^T [N,K] fp16, all 3 layers in one launch ----------------
__global__ void transconv_kernel(const float* __restrict__ W1,
                                 const float* __restrict__ W2,
                                 const float* __restrict__ W3) {
    __shared__ float t[32][33];
    const float* W = (blockIdx.z == 0) ? W1 : (blockIdx.z == 1) ? W2 : W3;
    size_t obase = (size_t)blockIdx.z * HDIM * HDIM;
    int bx = blockIdx.x * 32, by = blockIdx.y * 32;
    int x = threadIdx.x, y = threadIdx.y;   // 32 x 8
#pragma unroll
    for (int j = 0; j < 32; j += 8)
        t[y + j][x] = W[(size_t)(by + y + j) * HDIM + bx + x];
    __syncthreads();
#pragma unroll
    for (int j = 0; j < 32; j += 8) {
        size_t o = obase + (size_t)(bx + y + j) * HDIM + by + x;
        d_Wh[o] = __float2half_rn(t[x][y + j]);
    }
}

// ---------------- HMMA fp16x2 GEMM: C[M,512] = (Ah+Al) @ Bh^T, fp16 output ----------------
// Block tile 128x128, BK=64, 2-stage cp.async double buffer, 8 warps (2x4), warp tile 64x32.
// 3 tiles/stage (Ah, Al, Bh) -> 96KB/CTA -> 2 CTAs/SM.
#define TILE_B   16384                 // 128 rows x 64 fp16 x 2B (128B rows)
#define STAGE_B  (3 * TILE_B)          // Ah, Al, Bh
#define DYN_SMEM (2 * STAGE_B)         // 98304

__device__ __forceinline__ void load_tile(uint32_t smem_base,
                                          const __half* __restrict__ src,
                                          int row_base, int k0, int tid) {
    int row = tid >> 1;
    int c0  = (tid & 1) * 4;
    const __half* g = src + (size_t)(row_base + row) * HDIM + k0;
    uint32_t sb = smem_base + row * 128;
    int xr = row & 7;
#pragma unroll
    for (int c = c0; c < c0 + 4; ++c)
        cp_async16(sb + ((c ^ xr) << 4), g + c * 8);
}

__global__ __launch_bounds__(256, 2)
void gemm_f16x2_kernel(const __half* __restrict__ Ah, const __half* __restrict__ Al,
                       const __half* __restrict__ Bh,
                       __half* __restrict__ C, int M) {
    extern __shared__ __align__(1024) char dsm[];

    const int tid  = threadIdx.x;
    const int wid  = tid >> 5;
    const int lane = tid & 31;
    const int warp_m = wid >> 2;     // 0..1
    const int warp_n = wid & 3;      // 0..3
    const int block_row = blockIdx.x * 128;
    const int block_col = blockIdx.y * 128;

    uint32_t s_base = smem_u32(dsm);

    float acc[4][4][4];
#pragma unroll
    for (int i = 0; i < 4; i++)
#pragma unroll
        for (int j = 0; j < 4; j++)
#pragma unroll
            for (int q = 0; q < 4; q++) acc[i][j][q] = 0.0f;

    // prologue: stage 0 (k0=0), stage 1 (k0=64)
    {
        uint32_t st = s_base;
        load_tile(st,              Ah, block_row, 0, tid);
        load_tile(st + TILE_B,     Al, block_row, 0, tid);
        load_tile(st + 2 * TILE_B, Bh, block_col, 0, tid);
        CP_COMMIT();
        st = s_base + STAGE_B;
        load_tile(st,              Ah, block_row, 64, tid);
        load_tile(st + TILE_B,     Al, block_row, 64, tid);
        load_tile(st + 2 * TILE_B, Bh, block_col, 64, tid);
        CP_COMMIT();
    }

    // per-lane ldmatrix geometry (row&7 invariant under +16-row steps)
    const int a_row  = warp_m * 64 + (lane & 15);
    const int a_half = lane >> 4;
    const int a_x    = a_row & 7;
    const int b_row  = warp_n * 32 + (lane & 15);
    const int b_half = lane >> 4;
    const int b_x    = b_row & 7;

#pragma unroll 1
    for (int c = 0; c < 8; ++c) {
        CP_WAIT1();
        __syncthreads();
        uint32_t st  = s_base + (uint32_t)(c & 1) * STAGE_B;
        uint32_t sAh = st;
        uint32_t sAl = st + TILE_B;
        uint32_t sBh = st + 2 * TILE_B;

#pragma unroll
        for (int kk = 0; kk < 4; ++kk) {
            uint32_t a_chunk_off = (uint32_t)(((2 * kk + a_half) ^ a_x) << 4);
            uint32_t b_chunk_off = (uint32_t)(((2 * kk + b_half) ^ b_x) << 4);
            uint32_t ah[4][4], al[4][4];
#pragma unroll
            for (int i = 0; i < 4; ++i) {
                uint32_t ro = (uint32_t)(a_row + i * 16) * 128 + a_chunk_off;
                ldsm_x4(ah[i], sAh + ro);
                ldsm_x4(al[i], sAl + ro);
            }
            uint32_t bh[4][2];
#pragma unroll
            for (int p = 0; p < 2; ++p) {
                uint32_t ro = (uint32_t)(b_row + p * 16) * 128 + b_chunk_off;
                uint32_t r[4];
                ldsm_x4(r, sBh + ro);
                bh[2 * p][0] = r[0]; bh[2 * p][1] = r[2];
                bh[2 * p + 1][0] = r[1]; bh[2 * p + 1][1] = r[3];
            }
#pragma unroll
            for (int i = 0; i < 4; ++i)
#pragma unroll
                for (int j = 0; j < 4; ++j) {
                    mma_f16(acc[i][j], ah[i], bh[j]);
                    mma_f16(acc[i][j], al[i], bh[j]);
                }
        }
        __syncthreads();
        if (c + 2 < 8) {
            uint32_t st2 = s_base + (uint32_t)(c & 1) * STAGE_B;
            int k0 = (c + 2) * 64;
            load_tile(st2,              Ah, block_row, k0, tid);
            load_tile(st2 + TILE_B,     Al, block_row, k0, tid);
            load_tile(st2 + 2 * TILE_B, Bh, block_col, k0, tid);
        }
        CP_COMMIT();
    }

    // epilogue: fp16 stores (half2 per fragment pair)
    const int r_in = lane >> 2;
    const int c_in = (lane & 3) * 2;
#pragma unroll
    for (int i = 0; i < 4; ++i) {
        int row0 = block_row + warp_m * 64 + i * 16 + r_in;
#pragma unroll
        for (int j = 0; j < 4; ++j) {
            int col = block_col + warp_n * 32 + j * 8 + c_in;
            if (row0 < M)
                *(__half2*)(C + (size_t)row0 * HDIM + col) =
                    __floats2half2_rn(acc[i][j][0], acc[i][j][1]);
            if (row0 + 8 < M)
                *(__half2*)(C + (size_t)(row0 + 8) * HDIM + col) =
                    __floats2half2_rn(acc[i][j][2], acc[i][j][3]);
        }
    }
}

// ---------------- CSR SpMM (fp16 gather) + bias + ReLU + fp16 hi/lo split ----------------
// one block per row, 128 threads; each thread owns 4 features (8B fp16 per gather)
__global__ __launch_bounds__(128)
void spmm_relu_kernel(const float* __restrict__ bias) {
    int r = blockIdx.x;
    int t = threadIdx.x;
    int beg = d_rowptr[r];
    int end = d_rowptr[r + 1];
    float4 acc = make_float4(0.f, 0.f, 0.f, 0.f);
    int j = beg;
    for (; j + 3 < end; j += 4) {
        int2 e0 = d_epack[j],     e1 = d_epack[j + 1];
        int2 e2 = d_epack[j + 2], e3 = d_epack[j + 3];
        uint2 g0 = *(const uint2*)(d_s + (size_t)e0.x * HDIM + t * 4);
        uint2 g1 = *(const uint2*)(d_s + (size_t)e1.x * HDIM + t * 4);
        uint2 g2 = *(const uint2*)(d_s + (size_t)e2.x * HDIM + t * 4);
        uint2 g3 = *(const uint2*)(d_s + (size_t)e3.x * HDIM + t * 4);
        float v0 = __int_as_float(e0.y), v1 = __int_as_float(e1.y);
        float v2 = __int_as_float(e2.y), v3 = __int_as_float(e3.y);
        float2 a0 = __half22float2(*(__half2*)&g0.x), b0 = __half22float2(*(__half2*)&g0.y);
        float2 a1 = __half22float2(*(__half2*)&g1.x), b1 = __half22float2(*(__half2*)&g1.y);
        float2 a2 = __half22float2(*(__half2*)&g2.x), b2 = __half22float2(*(__half2*)&g2.y);
        float2 a3 = __half22float2(*(__half2*)&g3.x), b3 = __half22float2(*(__half2*)&g3.y);
        acc.x = fmaf(v0, a0.x, acc.x); acc.y = fmaf(v0, a0.y, acc.y);
        acc.z = fmaf(v0, b0.x, acc.z); acc.w = fmaf(v0, b0.y, acc.w);
        acc.x = fmaf(v1, a1.x, acc.x); acc.y = fmaf(v1, a1.y, acc.y);
        acc.z = fmaf(v1, b1.x, acc.z); acc.w = fmaf(v1, b1.y, acc.w);
        acc.x = fmaf(v2, a2.x, acc.x); acc.y = fmaf(v2, a2.y, acc.y);
        acc.z = fmaf(v2, b2.x, acc.z); acc.w = fmaf(v2, b2.y, acc.w);
        acc.x = fmaf(v3, a3.x, acc.x); acc.y = fmaf(v3, a3.y, acc.y);
        acc.z = fmaf(v3, b3.x, acc.z); acc.w = fmaf(v3, b3.y, acc.w);
    }
    for (; j < end; ++j) {
        int2 e0 = d_epack[j];
        float v0 = __int_as_float(e0.y);
        uint2 g0 = *(const uint2*)(d_s + (size_t)e0.x * HDIM + t * 4);
        float2 a0 = __half22float2(*(__half2*)&g0.x), b0 = __half22float2(*(__half2*)&g0.y);
        acc.x = fmaf(v0, a0.x, acc.x); acc.y = fmaf(v0, a0.y, acc.y);
        acc.z = fmaf(v0, b0.x, acc.z); acc.w = fmaf(v0, b0.y, acc.w);
    }
    float4 b = *(const float4*)(bias + t * 4);
    float h0 = fmaxf(acc.x + b.x, 0.f);
    float h1 = fmaxf(acc.y + b.y, 0.f);
    float h2 = fmaxf(acc.z + b.z, 0.f);
    float h3 = fmaxf(acc.w + b.w, 0.f);
    __half hh0 = __float2half_rn(h0);
    __half hh1 = __float2half_rn(h1);
    __half hh2 = __float2half_rn(h2);
    __half hh3 = __float2half_rn(h3);
    __half ll0 = __float2half_rn(h0 - __half2float(hh0));
    __half ll1 = __float2half_rn(h1 - __half2float(hh1));
    __half ll2 = __float2half_rn(h2 - __half2float(hh2));
    __half ll3 = __float2half_rn(h3 - __half2float(hh3));
    __half2* H = (__half2*)(d_Ah + (size_t)r * HDIM + t * 4);
    __half2* L = (__half2*)(d_Al + (size_t)r * HDIM + t * 4);
    H[0] = __halves2half2(hh0, hh1);
    H[1] = __halves2half2(hh2, hh3);
    L[0] = __halves2half2(ll0, ll1);
    L[1] = __halves2half2(ll2, ll3);
}

// ---------------- pooling: reads hi/lo (v = hi + lo) ----------------
__global__ __launch_bounds__(256)
void pool_kernel() {
    int f2 = threadIdx.x;               // feature pair 0..255
    const __half2* H = (const __half2*)d_Ah;
    const __half2* L = (const __half2*)d_Al;
    float mx0 = 0.f, mx1 = 0.f, sm0 = 0.f, sm1 = 0.f;
    for (int n = blockIdx.x; n < NNODES; n += gridDim.x) {
        __half2 h = H[(size_t)n * 256 + f2];
        __half2 l = L[(size_t)n * 256 + f2];
        float v0 = __half2float(h.x) + __half2float(l.x);
        float v1 = __half2float(h.y) + __half2float(l.y);
        mx0 = fmaxf(mx0, v0); sm0 += v0;
        mx1 = fmaxf(mx1, v1); sm1 += v1;
    }
    atomicMax(&d_gmax[2 * f2],     __float_as_uint(mx0));   // valid: values >= 0
    atomicMax(&d_gmax[2 * f2 + 1], __float_as_uint(mx1));
    atomicAdd(&d_gsum[2 * f2],     sm0);
    atomicAdd(&d_gsum[2 * f2 + 1], sm1);
}

__global__ void combine_kernel() {
    int f = threadIdx.x;
    d_g[f]       += __uint_as_float(d_gmax[f]);
    d_g[512 + f] += d_gsum[f] * (1.0f / (float)NNODES);
    d_gmax[f] = 0u;
    d_gsum[f] = 0.0f;
}

// ---------------- MLP head + log_softmax ----------------
__global__ __launch_bounds__(128)
void head_kernel(const float* __restrict__ l1W, const float* __restrict__ l1b,
                 const float* __restrict__ l2W, const float* __restrict__ l2b,
                 const float* __restrict__ l3W, const float* __restrict__ l3b,
                 float* __restrict__ out) {
    __shared__ float y1[128];
    __shared__ float y2[64];
    __shared__ float y3[10];
    int t = threadIdx.x;
    {
        float acc = 0.0f;
        for (int i = 0; i < 1024; i++)
            acc = fmaf(d_g[i], l1W[i * 128 + t], acc);
        y1[t] = fmaxf(acc + l1b[t], 0.0f);
    }
    __syncthreads();
    if (t < 64) {
        float acc = 0.0f;
#pragma unroll 8
        for (int i = 0; i < 128; i++)
            acc = fmaf(y1[i], l2W[i * 64 + t], acc);
        y2[t] = fmaxf(acc + l2b[t], 0.0f);
    }
    __syncthreads();
    if (t < 10) {
        float acc = 0.0f;
#pragma unroll
        for (int i = 0; i < 64; i++)
            acc = fmaf(y2[i], l3W[i * 10 + t], acc);
        y3[t] = acc + l3b[t];
    }
    __syncthreads();
    if (t == 0) {
        float m = -1e30f;
#pragma unroll
        for (int j = 0; j < 10; j++) m = fmaxf(m, y3[j]);
        float s = 0.0f;
#pragma unroll
        for (int j = 0; j < 10; j++) s += expf(y3[j] - m);
        float lse = m + logf(s);
#pragma unroll
        for (int j = 0; j < 10; j++) out[j] = y3[j] - lse;
    }
}

// ---------------- launch (multi-stream fork/join under graph capture) ----------------
extern "C" void kernel_launch(void* const* d_in, const int* in_sizes, int n_in,
                              void* d_out, int out_size) {
    const float* x        = (const float*)d_in[0];
    const int*   rows     = (const int*)  d_in[1];
    const int*   cols     = (const int*)  d_in[2];
    const float* adj_vals = (const float*)d_in[3];
    const float* W1 = (const float*)d_in[4];
    const float* b1 = (const float*)d_in[5];
    const float* W2 = (const float*)d_in[6];
    const float* b2 = (const float*)d_in[7];
    const float* W3 = (const float*)d_in[8];
    const float* b3 = (const float*)d_in[9];
    const float* l1W = (const float*)d_in[10];
    const float* l1b = (const float*)d_in[11];
    const float* l2W = (const float*)d_in[12];
    const float* l2b = (const float*)d_in[13];
    const float* l3W = (const float*)d_in[14];
    const float* l3b = (const float*)d_in[15];
    float* out = (float*)d_out;

    __half *s_g, *Ah_g, *Al_g, *Wh_g;
    cudaGetSymbolAddress((void**)&s_g,  d_s);
    cudaGetSymbolAddress((void**)&Ah_g, d_Ah);
    cudaGetSymbolAddress((void**)&Al_g, d_Al);
    cudaGetSymbolAddress((void**)&Wh_g, d_Wh);

    // one-time host-object setup (streams/events are not device memory)
    static bool once = false;
    static cudaStream_t sCSR, sPool;
    static cudaEvent_t evFork, evCSR, evSpmm[3], evPool[3], evDone;
    if (!once) {
        cudaFuncSetAttribute(gemm_f16x2_kernel,
                             cudaFuncAttributeMaxDynamicSharedMemorySize, DYN_SMEM);
        cudaStreamCreateWithFlags(&sCSR,  cudaStreamNonBlocking);
        cudaStreamCreateWithFlags(&sPool, cudaStreamNonBlocking);
        cudaEventCreateWithFlags(&evFork, cudaEventDisableTiming);
        cudaEventCreateWithFlags(&evCSR,  cudaEventDisableTiming);
        cudaEventCreateWithFlags(&evDone, cudaEventDisableTiming);
        for (int i = 0; i < 3; i++) {
            cudaEventCreateWithFlags(&evSpmm[i], cudaEventDisableTiming);
            cudaEventCreateWithFlags(&evPool[i], cudaEventDisableTiming);
        }
        once = true;
    }

    const size_t WOFF = (size_t)HDIM * HDIM;
    const float* bb[3] = {b1, b2, b3};
    cudaStream_t s0 = 0;   // capture-origin (default) stream

    // fork side streams from capture stream
    cudaEventRecord(evFork, s0);
    cudaStreamWaitEvent(sCSR, evFork, 0);
    cudaStreamWaitEvent(sPool, evFork, 0);

    dim3 gemm_grid((NNODES + 127) / 128, HDIM / 128);   // (157, 4)

    // main stream: weight prep + layer-1 input conversion
    transconv_kernel<<<dim3(16, 16, 3), dim3(32, 8), 0, s0>>>(W1, W2, W3);
    convert_hilo_kernel<<<(NNODES * HDIM / 4 + 255) / 256, 256, 0, s0>>>(x, NNODES * HDIM / 4);

    // side stream: CSR build
    init_kernel<<<(NNODES + 255) / 256, 256, 0, sCSR>>>();
    hist_kernel<<<(NEDGES + 255) / 256, 256, 0, sCSR>>>(rows);
    scan_kernel<<<1, 1024, 0, sCSR>>>();

    // layer-1 GEMM
    gemm_f16x2_kernel<<<gemm_grid, 256, DYN_SMEM, s0>>>(Ah_g, Al_g, Wh_g, s_g, NNODES);

    scatter_kernel<<<(NEDGES + 255) / 256, 256, 0, sCSR>>>(rows, cols, adj_vals);
    cudaEventRecord(evCSR, sCSR);

    for (int L = 0; L < 3; ++L) {
        if (L > 0)
            gemm_f16x2_kernel<<<gemm_grid, 256, DYN_SMEM, s0>>>(
                Ah_g, Al_g, Wh_g + L * WOFF, s_g, NNODES);
        if (L == 0) cudaStreamWaitEvent(s0, evCSR, 0);          // CSR ready before SpMM1
        else        cudaStreamWaitEvent(s0, evPool[L - 1], 0);  // pool(L-1) done reading d_Ah
        spmm_relu_kernel<<<NNODES, 128, 0, s0>>>(bb[L]);
        cudaEventRecord(evSpmm[L], s0);

        // pool + combine on side stream, overlapped with next GEMM
        cudaStreamWaitEvent(sPool, evSpmm[L], 0);
        pool_kernel<<<256, 256, 0, sPool>>>();
        cudaEventRecord(evPool[L], sPool);
        combine_kernel<<<1, 512, 0, sPool>>>();
    }

    // join: head needs combine3 (d_g complete)
    cudaEventRecord(evDone, sPool);
    cudaStreamWaitEvent(s0, evDone, 0);
    head_kernel<<<1, 128, 0, s0>>>(l1W, l1b, l2W, l2b, l3W, l3b, out);
}

// round 9
// speedup vs baseline: 1.9291x; 1.3256x over previous
#include <cuda_runtime.h>
#include <cuda_fp16.h>
#include <math.h>
#include <stdint.h>

// Problem constants (fixed by the reference)
#define NNODES 20000
#define NEDGES 320000
#define HDIM   512
#define NPAD   20096            // 157 * 128, padded row count for GEMM tiles

// ---------------- scratch (device globals; no runtime allocation) ----------------
__device__ __half   d_s [NNODES * HDIM];       // GEMM output (fp16)
__device__ __half   d_Ah[NPAD * HDIM];         // activation (fp16), padded
__device__ __half   d_Wh[3 * HDIM * HDIM];     // W^T (fp16), [N,K] layout, 3 layers
__device__ int      d_counts[NNODES];
__device__ int      d_rowptr[NNODES + 1];
__device__ int      d_rowoff[NNODES];
__device__ int2     d_epack[NEDGES];       // (col, float-bits(val))
__device__ float    d_g[1024];             // accumulated [max | mean] over 3 layers
__device__ unsigned d_gmax[HDIM];
__device__ float    d_gsum[HDIM];

// ================= PTX helpers (generic compute_103-safe) =================
__device__ __forceinline__ uint32_t smem_u32(const void* p) {
    uint32_t a;
    asm("{ .reg .u64 t; cvta.to.shared.u64 t, %1; cvt.u32.u64 %0, t; }" : "=r"(a) : "l"(p));
    return a;
}
__device__ __forceinline__ void cp_async16(uint32_t dst, const void* src) {
    asm volatile("cp.async.cg.shared.global [%0], [%1], 16;" :: "r"(dst), "l"(src));
}
#define CP_COMMIT() asm volatile("cp.async.commit_group;" ::: "memory")
#define CP_WAIT1()  asm volatile("cp.async.wait_group 1;" ::: "memory")

__device__ __forceinline__ void ldsm_x4(uint32_t* r, uint32_t addr) {
    asm volatile("ldmatrix.sync.aligned.m8n8.x4.shared.b16 {%0,%1,%2,%3}, [%4];"
        : "=r"(r[0]), "=r"(r[1]), "=r"(r[2]), "=r"(r[3]) : "r"(addr));
}
__device__ __forceinline__ void mma_f16(float* c, const uint32_t* a, const uint32_t* b) {
    asm volatile(
        "mma.sync.aligned.m16n8k16.row.col.f32.f16.f16.f32 "
        "{%0,%1,%2,%3}, {%4,%5,%6,%7}, {%8,%9}, {%0,%1,%2,%3};"
        : "+f"(c[0]), "+f"(c[1]), "+f"(c[2]), "+f"(c[3])
        : "r"(a[0]), "r"(a[1]), "r"(a[2]), "r"(a[3]), "r"(b[0]), "r"(b[1]));
}

// ---------------- init: zero counters / accumulators ----------------
__global__ void init_kernel() {
    int i = blockIdx.x * blockDim.x + threadIdx.x;
    if (i < NNODES) d_counts[i] = 0;
    if (i < 1024)   d_g[i] = 0.0f;
    if (i < HDIM) { d_gmax[i] = 0u; d_gsum[i] = 0.0f; }
}

// ---------------- CSR build ----------------
__global__ void hist_kernel(const int* __restrict__ rows) {
    int e = blockIdx.x * blockDim.x + threadIdx.x;
    if (e < NEDGES) atomicAdd(&d_counts[rows[e]], 1);
}

// single-block scan over 20000 counts -> rowptr (+ rowoff copy fused)
__global__ void scan_kernel() {
    __shared__ int sums[1024];
    const int CH = 20;
    int t = threadIdx.x;
    int base = t * CH;
    int local[CH];
    int run = 0;
#pragma unroll
    for (int i = 0; i < CH; i++) {
        int idx = base + i;
        int v = (idx < NNODES) ? d_counts[idx] : 0;
        run += v;
        local[i] = run;
    }
    sums[t] = run;
    __syncthreads();
    for (int off = 1; off < 1024; off <<= 1) {
        int v = 0;
        if (t >= off) v = sums[t - off];
        __syncthreads();
        if (t >= off) sums[t] += v;
        __syncthreads();
    }
    int offset = (t > 0) ? sums[t - 1] : 0;
#pragma unroll
    for (int i = 0; i < CH; i++) {
        int idx = base + i;
        if (idx < NNODES) {
            d_rowptr[idx + 1] = offset + local[i];
            d_rowoff[idx] = (i == 0) ? offset : offset + local[i - 1];
        }
    }
    if (t == 0) d_rowptr[0] = 0;
}

__global__ void scatter_kernel(const int* __restrict__ rows,
                               const int* __restrict__ cols,
                               const float* __restrict__ vals) {
    int e = blockIdx.x * blockDim.x + threadIdx.x;
    if (e < NEDGES) {
        int r = rows[e];
        int p = atomicAdd(&d_rowoff[r], 1);
        d_epack[p] = make_int2(cols[e], __float_as_int(vals[e]));
    }
}

// ---------------- fp32 -> fp16 convert (layer-1 input only) ----------------
__global__ void convert_kernel(const float* __restrict__ src, int n4) {
    int i = blockIdx.x * blockDim.x + threadIdx.x;
    if (i >= n4) return;
    float4 v = ((const float4*)src)[i];
    ((__half2*)d_Ah)[2 * i]     = __floats2half2_rn(v.x, v.y);
    ((__half2*)d_Ah)[2 * i + 1] = __floats2half2_rn(v.z, v.w);
}

// ---------------- W [K,N] -> W^T [N,K] fp16, all 3 layers in one launch ----------------
__global__ void transconv_kernel(const float* __restrict__ W1,
                                 const float* __restrict__ W2,
                                 const float* __restrict__ W3) {
    __shared__ float t[32][33];
    const float* W = (blockIdx.z == 0) ? W1 : (blockIdx.z == 1) ? W2 : W3;
    size_t obase = (size_t)blockIdx.z * HDIM * HDIM;
    int bx = blockIdx.x * 32, by = blockIdx.y * 32;
    int x = threadIdx.x, y = threadIdx.y;   // 32 x 8
#pragma unroll
    for (int j = 0; j < 32; j += 8)
        t[y + j][x] = W[(size_t)(by + y + j) * HDIM + bx + x];
    __syncthreads();
#pragma unroll
    for (int j = 0; j < 32; j += 8) {
        size_t o = obase + (size_t)(bx + y + j) * HDIM + by + x;
        d_Wh[o] = __float2half_rn(t[x][y + j]);
    }
}

// ---------------- HMMA fp16 GEMM: C[M,512] = A @ B^T, fp16 in/out ----------------
// Block tile 128x128, BK=64, 2-stage cp.async double buffer, 8 warps (2x4), warp tile 64x32.
// 2 tiles/stage (A, B) -> 64KB/CTA -> 2 CTAs/SM (reg-limited).
#define TILE_B   16384                 // 128 rows x 64 fp16 x 2B (128B rows)
#define STAGE_B  (2 * TILE_B)          // A, B
#define DYN_SMEM (2 * STAGE_B)         // 65536

__device__ __forceinline__ void load_tile(uint32_t smem_base,
                                          const __half* __restrict__ src,
                                          int row_base, int k0, int tid) {
    int row = tid >> 1;
    int c0  = (tid & 1) * 4;
    const __half* g = src + (size_t)(row_base + row) * HDIM + k0;
    uint32_t sb = smem_base + row * 128;
    int xr = row & 7;
#pragma unroll
    for (int c = c0; c < c0 + 4; ++c)
        cp_async16(sb + ((c ^ xr) << 4), g + c * 8);
}

__global__ __launch_bounds__(256, 2)
void gemm_f16_kernel(const __half* __restrict__ A, const __half* __restrict__ Bh,
                     __half* __restrict__ C, int M) {
    extern __shared__ __align__(1024) char dsm[];

    const int tid  = threadIdx.x;
    const int wid  = tid >> 5;
    const int lane = tid & 31;
    const int warp_m = wid >> 2;     // 0..1
    const int warp_n = wid & 3;      // 0..3
    const int block_row = blockIdx.x * 128;
    const int block_col = blockIdx.y * 128;

    uint32_t s_base = smem_u32(dsm);

    float acc[4][4][4];
#pragma unroll
    for (int i = 0; i < 4; i++)
#pragma unroll
        for (int j = 0; j < 4; j++)
#pragma unroll
            for (int q = 0; q < 4; q++) acc[i][j][q] = 0.0f;

    // prologue: stage 0 (k0=0), stage 1 (k0=64)
    {
        uint32_t st = s_base;
        load_tile(st,          A,  block_row, 0, tid);
        load_tile(st + TILE_B, Bh, block_col, 0, tid);
        CP_COMMIT();
        st = s_base + STAGE_B;
        load_tile(st,          A,  block_row, 64, tid);
        load_tile(st + TILE_B, Bh, block_col, 64, tid);
        CP_COMMIT();
    }

    // per-lane ldmatrix geometry (row&7 invariant under +16-row steps)
    const int a_row  = warp_m * 64 + (lane & 15);
    const int a_half = lane >> 4;
    const int a_x    = a_row & 7;
    const int b_row  = warp_n * 32 + (lane & 15);
    const int b_half = lane >> 4;
    const int b_x    = b_row & 7;

#pragma unroll 1
    for (int c = 0; c < 8; ++c) {
        CP_WAIT1();
        __syncthreads();
        uint32_t st  = s_base + (uint32_t)(c & 1) * STAGE_B;
        uint32_t sA  = st;
        uint32_t sBh = st + TILE_B;

#pragma unroll
        for (int kk = 0; kk < 4; ++kk) {
            uint32_t a_chunk_off = (uint32_t)(((2 * kk + a_half) ^ a_x) << 4);
            uint32_t b_chunk_off = (uint32_t)(((2 * kk + b_half) ^ b_x) << 4);
            uint32_t ah[4][4];
#pragma unroll
            for (int i = 0; i < 4; ++i) {
                uint32_t ro = (uint32_t)(a_row + i * 16) * 128 + a_chunk_off;
                ldsm_x4(ah[i], sA + ro);
            }
            uint32_t bh[4][2];
#pragma unroll
            for (int p = 0; p < 2; ++p) {
                uint32_t ro = (uint32_t)(b_row + p * 16) * 128 + b_chunk_off;
                uint32_t r[4];
                ldsm_x4(r, sBh + ro);
                bh[2 * p][0] = r[0]; bh[2 * p][1] = r[2];
                bh[2 * p + 1][0] = r[1]; bh[2 * p + 1][1] = r[3];
            }
#pragma unroll
            for (int i = 0; i < 4; ++i)
#pragma unroll
                for (int j = 0; j < 4; ++j)
                    mma_f16(acc[i][j], ah[i], bh[j]);
        }
        __syncthreads();
        if (c + 2 < 8) {
            uint32_t st2 = s_base + (uint32_t)(c & 1) * STAGE_B;
            int k0 = (c + 2) * 64;
            load_tile(st2,          A,  block_row, k0, tid);
            load_tile(st2 + TILE_B, Bh, block_col, k0, tid);
        }
        CP_COMMIT();
    }

    // epilogue: fp16 stores (half2 per fragment pair)
    const int r_in = lane >> 2;
    const int c_in = (lane & 3) * 2;
#pragma unroll
    for (int i = 0; i < 4; ++i) {
        int row0 = block_row + warp_m * 64 + i * 16 + r_in;
#pragma unroll
        for (int j = 0; j < 4; ++j) {
            int col = block_col + warp_n * 32 + j * 8 + c_in;
            if (row0 < M)
                *(__half2*)(C + (size_t)row0 * HDIM + col) =
                    __floats2half2_rn(acc[i][j][0], acc[i][j][1]);
            if (row0 + 8 < M)
                *(__half2*)(C + (size_t)(row0 + 8) * HDIM + col) =
                    __floats2half2_rn(acc[i][j][2], acc[i][j][3]);
        }
    }
}

// ---------------- CSR SpMM (fp16 gather) + bias + ReLU -> fp16 activation ----------------
// one block per row, 128 threads; each thread owns 4 features (8B fp16 per gather)
__global__ __launch_bounds__(128)
void spmm_relu_kernel(const float* __restrict__ bias) {
    int r = blockIdx.x;
    int t = threadIdx.x;
    int beg = d_rowptr[r];
    int end = d_rowptr[r + 1];
    float4 acc = make_float4(0.f, 0.f, 0.f, 0.f);
    int j = beg;
    for (; j + 3 < end; j += 4) {
        int2 e0 = d_epack[j],     e1 = d_epack[j + 1];
        int2 e2 = d_epack[j + 2], e3 = d_epack[j + 3];
        uint2 g0 = *(const uint2*)(d_s + (size_t)e0.x * HDIM + t * 4);
        uint2 g1 = *(const uint2*)(d_s + (size_t)e1.x * HDIM + t * 4);
        uint2 g2 = *(const uint2*)(d_s + (size_t)e2.x * HDIM + t * 4);
        uint2 g3 = *(const uint2*)(d_s + (size_t)e3.x * HDIM + t * 4);
        float v0 = __int_as_float(e0.y), v1 = __int_as_float(e1.y);
        float v2 = __int_as_float(e2.y), v3 = __int_as_float(e3.y);
        float2 a0 = __half22float2(*(__half2*)&g0.x), b0 = __half22float2(*(__half2*)&g0.y);
        float2 a1 = __half22float2(*(__half2*)&g1.x), b1 = __half22float2(*(__half2*)&g1.y);
        float2 a2 = __half22float2(*(__half2*)&g2.x), b2 = __half22float2(*(__half2*)&g2.y);
        float2 a3 = __half22float2(*(__half2*)&g3.x), b3 = __half22float2(*(__half2*)&g3.y);
        acc.x = fmaf(v0, a0.x, acc.x); acc.y = fmaf(v0, a0.y, acc.y);
        acc.z = fmaf(v0, b0.x, acc.z); acc.w = fmaf(v0, b0.y, acc.w);
        acc.x = fmaf(v1, a1.x, acc.x); acc.y = fmaf(v1, a1.y, acc.y);
        acc.z = fmaf(v1, b1.x, acc.z); acc.w = fmaf(v1, b1.y, acc.w);
        acc.x = fmaf(v2, a2.x, acc.x); acc.y = fmaf(v2, a2.y, acc.y);
        acc.z = fmaf(v2, b2.x, acc.z); acc.w = fmaf(v2, b2.y, acc.w);
        acc.x = fmaf(v3, a3.x, acc.x); acc.y = fmaf(v3, a3.y, acc.y);
        acc.z = fmaf(v3, b3.x, acc.z); acc.w = fmaf(v3, b3.y, acc.w);
    }
    for (; j < end; ++j) {
        int2 e0 = d_epack[j];
        float v0 = __int_as_float(e0.y);
        uint2 g0 = *(const uint2*)(d_s + (size_t)e0.x * HDIM + t * 4);
        float2 a0 = __half22float2(*(__half2*)&g0.x), b0 = __half22float2(*(__half2*)&g0.y);
        acc.x = fmaf(v0, a0.x, acc.x); acc.y = fmaf(v0, a0.y, acc.y);
        acc.z = fmaf(v0, b0.x, acc.z); acc.w = fmaf(v0, b0.y, acc.w);
    }
    float4 b = *(const float4*)(bias + t * 4);
    float h0 = fmaxf(acc.x + b.x, 0.f);
    float h1 = fmaxf(acc.y + b.y, 0.f);
    float h2 = fmaxf(acc.z + b.z, 0.f);
    float h3 = fmaxf(acc.w + b.w, 0.f);
    __half2* H = (__half2*)(d_Ah + (size_t)r * HDIM + t * 4);
    H[0] = __floats2half2_rn(h0, h1);
    H[1] = __floats2half2_rn(h2, h3);
}

// ---------------- pooling: reads fp16 activation ----------------
__global__ __launch_bounds__(256)
void pool_kernel() {
    int f2 = threadIdx.x;               // feature pair 0..255
    const __half2* H = (const __half2*)d_Ah;
    float mx0 = 0.f, mx1 = 0.f, sm0 = 0.f, sm1 = 0.f;
    for (int n = blockIdx.x; n < NNODES; n += gridDim.x) {
        __half2 h = H[(size_t)n * 256 + f2];
        float v0 = __half2float(h.x);
        float v1 = __half2float(h.y);
        mx0 = fmaxf(mx0, v0); sm0 += v0;
        mx1 = fmaxf(mx1, v1); sm1 += v1;
    }
    atomicMax(&d_gmax[2 * f2],     __float_as_uint(mx0));   // valid: values >= 0
    atomicMax(&d_gmax[2 * f2 + 1], __float_as_uint(mx1));
    atomicAdd(&d_gsum[2 * f2],     sm0);
    atomicAdd(&d_gsum[2 * f2 + 1], sm1);
}

__global__ void combine_kernel() {
    int f = threadIdx.x;
    d_g[f]       += __uint_as_float(d_gmax[f]);
    d_g[512 + f] += d_gsum[f] * (1.0f / (float)NNODES);
    d_gmax[f] = 0u;
    d_gsum[f] = 0.0f;
}

// ---------------- MLP head + log_softmax ----------------
__global__ __launch_bounds__(128)
void head_kernel(const float* __restrict__ l1W, const float* __restrict__ l1b,
                 const float* __restrict__ l2W, const float* __restrict__ l2b,
                 const float* __restrict__ l3W, const float* __restrict__ l3b,
                 float* __restrict__ out) {
    __shared__ float y1[128];
    __shared__ float y2[64];
    __shared__ float y3[10];
    int t = threadIdx.x;
    {
        float acc = 0.0f;
        for (int i = 0; i < 1024; i++)
            acc = fmaf(d_g[i], l1W[i * 128 + t], acc);
        y1[t] = fmaxf(acc + l1b[t], 0.0f);
    }
    __syncthreads();
    if (t < 64) {
        float acc = 0.0f;
#pragma unroll 8
        for (int i = 0; i < 128; i++)
            acc = fmaf(y1[i], l2W[i * 64 + t], acc);
        y2[t] = fmaxf(acc + l2b[t], 0.0f);
    }
    __syncthreads();
    if (t < 10) {
        float acc = 0.0f;
#pragma unroll
        for (int i = 0; i < 64; i++)
            acc = fmaf(y2[i], l3W[i * 10 + t], acc);
        y3[t] = acc + l3b[t];
    }
    __syncthreads();
    if (t == 0) {
        float m = -1e30f;
#pragma unroll
        for (int j = 0; j < 10; j++) m = fmaxf(m, y3[j]);
        float s = 0.0f;
#pragma unroll
        for (int j = 0; j < 10; j++) s += expf(y3[j] - m);
        float lse = m + logf(s);
#pragma unroll
        for (int j = 0; j < 10; j++) out[j] = y3[j] - lse;
    }
}

// ---------------- launch (multi-stream fork/join under graph capture) ----------------
extern "C" void kernel_launch(void* const* d_in, const int* in_sizes, int n_in,
                              void* d_out, int out_size) {
    const float* x        = (const float*)d_in[0];
    const int*   rows     = (const int*)  d_in[1];
    const int*   cols     = (const int*)  d_in[2];
    const float* adj_vals = (const float*)d_in[3];
    const float* W1 = (const float*)d_in[4];
    const float* b1 = (const float*)d_in[5];
    const float* W2 = (const float*)d_in[6];
    const float* b2 = (const float*)d_in[7];
    const float* W3 = (const float*)d_in[8];
    const float* b3 = (const float*)d_in[9];
    const float* l1W = (const float*)d_in[10];
    const float* l1b = (const float*)d_in[11];
    const float* l2W = (const float*)d_in[12];
    const float* l2b = (const float*)d_in[13];
    const float* l3W = (const float*)d_in[14];
    const float* l3b = (const float*)d_in[15];
    float* out = (float*)d_out;

    __half *s_g, *Ah_g, *Wh_g;
    cudaGetSymbolAddress((void**)&s_g,  d_s);
    cudaGetSymbolAddress((void**)&Ah_g, d_Ah);
    cudaGetSymbolAddress((void**)&Wh_g, d_Wh);

    // one-time host-object setup (streams/events are not device memory)
    static bool once = false;
    static cudaStream_t sCSR, sPool;
    static cudaEvent_t evFork, evCSR, evSpmm[3], evPool[3], evDone;
    if (!once) {
        cudaFuncSetAttribute(gemm_f16_kernel,
                             cudaFuncAttributeMaxDynamicSharedMemorySize, DYN_SMEM);
        cudaStreamCreateWithFlags(&sCSR,  cudaStreamNonBlocking);
        cudaStreamCreateWithFlags(&sPool, cudaStreamNonBlocking);
        cudaEventCreateWithFlags(&evFork, cudaEventDisableTiming);
        cudaEventCreateWithFlags(&evCSR,  cudaEventDisableTiming);
        cudaEventCreateWithFlags(&evDone, cudaEventDisableTiming);
        for (int i = 0; i < 3; i++) {
            cudaEventCreateWithFlags(&evSpmm[i], cudaEventDisableTiming);
            cudaEventCreateWithFlags(&evPool[i], cudaEventDisableTiming);
        }
        once = true;
    }

    const size_t WOFF = (size_t)HDIM * HDIM;
    const float* bb[3] = {b1, b2, b3};
    cudaStream_t s0 = 0;   // capture-origin (default) stream

    // fork side streams from capture stream
    cudaEventRecord(evFork, s0);
    cudaStreamWaitEvent(sCSR, evFork, 0);
    cudaStreamWaitEvent(sPool, evFork, 0);

    dim3 gemm_grid((NNODES + 127) / 128, HDIM / 128);   // (157, 4)

    // main stream: weight prep + layer-1 input conversion
    transconv_kernel<<<dim3(16, 16, 3), dim3(32, 8), 0, s0>>>(W1, W2, W3);
    convert_kernel<<<(NNODES * HDIM / 4 + 255) / 256, 256, 0, s0>>>(x, NNODES * HDIM / 4);

    // side stream: CSR build
    init_kernel<<<(NNODES + 255) / 256, 256, 0, sCSR>>>();
    hist_kernel<<<(NEDGES + 255) / 256, 256, 0, sCSR>>>(rows);
    scan_kernel<<<1, 1024, 0, sCSR>>>();

    // layer-1 GEMM
    gemm_f16_kernel<<<gemm_grid, 256, DYN_SMEM, s0>>>(Ah_g, Wh_g, s_g, NNODES);

    scatter_kernel<<<(NEDGES + 255) / 256, 256, 0, sCSR>>>(rows, cols, adj_vals);
    cudaEventRecord(evCSR, sCSR);

    for (int L = 0; L < 3; ++L) {
        if (L > 0)
            gemm_f16_kernel<<<gemm_grid, 256, DYN_SMEM, s0>>>(
                Ah_g, Wh_g + L * WOFF, s_g, NNODES);
        if (L == 0) cudaStreamWaitEvent(s0, evCSR, 0);          // CSR ready before SpMM1
        else        cudaStreamWaitEvent(s0, evPool[L - 1], 0);  // pool(L-1) done reading d_Ah
        spmm_relu_kernel<<<NNODES, 128, 0, s0>>>(bb[L]);
        cudaEventRecord(evSpmm[L], s0);

        // pool + combine on side stream, overlapped with next GEMM
        cudaStreamWaitEvent(sPool, evSpmm[L], 0);
        pool_kernel<<<256, 256, 0, sPool>>>();
        cudaEventRecord(evPool[L], sPool);
        combine_kernel<<<1, 512, 0, sPool>>>();
    }

    // join: head needs combine3 (d_g complete)
    cudaEventRecord(evDone, sPool);
    cudaStreamWaitEvent(s0, evDone, 0);
    head_kernel<<<1, 128, 0, s0>>>(l1W, l1b, l2W, l2b, l3W, l3b, out);
}